// round 14
// baseline (speedup 1.0000x reference)
#include <cuda_runtime.h>
#include <cuda_bf16.h>
#include <cstdint>

#define BB 32
#define PP 4096
#define QQ 64
#define DD 128
#define NT 9
#define NEGBIG (-1e30f)
#define POSBIG (1e30f)

// ---- main kernel smem layout (32-bit words) ----
#define SM_UHI   0        // U hi packed  [qp*136 + d]   32*136 = 4352
#define SM_ULO   4352     // U lo packed                  4352
#define SM_VTHI  8704     // Vt hi packed [dp*72 + q]    64*72  = 4608
#define SM_VTLO  13312    // Vt lo packed                 4608
#define SM_HC    17920    // per warp c2q half buffer 16*68 = 1088; 8*1088 = 8704
#define SM_MZ    26624    // per warp row (m,z) 16*2      8*32 = 256
#define SM_TOK   26880    // tok ints                     512
#define SM_MZS   27392    // warp M/Z                     16
#define SM_TOTAL 27408
#define SMEM_BYTES (SM_TOTAL * 4)

// device scratch (zero-initialized)
__device__ float g_Vt[BB * DD * QQ];      // Vt[b][d][q]
__device__ float g_part[BB * NT * 1024];  // per (b,tile) partials
__device__ int   g_cnt[BB];               // arrival counters (left 0 after each call)

// ---------------------------------------------------------------------------
__device__ __forceinline__ void mma_bf16(float* d,
    uint32_t a0, uint32_t a1, uint32_t a2, uint32_t a3,
    uint32_t b0, uint32_t b1)
{
    asm volatile(
        "mma.sync.aligned.m16n8k16.row.col.f32.bf16.bf16.f32 "
        "{%0,%1,%2,%3}, {%4,%5,%6,%7}, {%8,%9}, {%0,%1,%2,%3};"
        : "+f"(d[0]), "+f"(d[1]), "+f"(d[2]), "+f"(d[3])
        : "r"(a0), "r"(a1), "r"(a2), "r"(a3), "r"(b0), "r"(b1));
}

// split (x0,x1) into packed bf16x2 hi and lo (x = hi + lo + O(2^-17 x))
__device__ __forceinline__ void packsplit(float x0, float x1, uint32_t& hi, uint32_t& lo) {
    __nv_bfloat162 h = __float22bfloat162_rn(make_float2(x0, x1));
    float2 hf = __bfloat1622float2(h);
    __nv_bfloat162 l = __float22bfloat162_rn(make_float2(x0 - hf.x, x1 - hf.y));
    hi = *reinterpret_cast<uint32_t*>(&h);
    lo = *reinterpret_cast<uint32_t*>(&l);
}

// ---------------------------------------------------------------------------
// Kernel 1: Vt[b][d][q] = sum_e W[d,e]*U[b,q,e] (fp32 exact). grid (8,32).
// ---------------------------------------------------------------------------
__global__ void vt_kernel(const float* __restrict__ U, const float* __restrict__ W) {
    __shared__ float U_s[QQ * 129];
    __shared__ float W_s[16 * DD];
    int b = blockIdx.y, dbase = blockIdx.x * 16, tid = threadIdx.x;

    const float* Ub = U + (size_t)b * QQ * DD;
    for (int i = tid; i < QQ * DD; i += 256)
        U_s[(i >> 7) * 129 + (i & 127)] = Ub[i];
    for (int i = tid; i < 16 * DD; i += 256)
        W_s[i] = W[(size_t)dbase * DD + i];
    __syncthreads();

    int q = tid & 63, dg = tid >> 6;
    float acc[4] = {0.f, 0.f, 0.f, 0.f};
#pragma unroll 4
    for (int e = 0; e < DD; e++) {
        float u = U_s[q * 129 + e];
#pragma unroll
        for (int k = 0; k < 4; k++)
            acc[k] += u * W_s[(dg * 4 + k) * DD + e];
    }
#pragma unroll
    for (int k = 0; k < 4; k++)
        g_Vt[((size_t)b * DD + dbase + dg * 4 + k) * QQ + q] = acc[k];
}

// ---------------------------------------------------------------------------
// Kernel 2: fused attention (bf16-split MMA) + pooling + fused finalize.
// grid (NT=9, 32), 256 threads, 2 CTAs/SM. Tiles 0-4: 4 chunks; 5-8: 3 chunks.
// ---------------------------------------------------------------------------
__global__ void __launch_bounds__(256, 2) main_kernel(
    const float* __restrict__ H, const float* __restrict__ U,
    const float* __restrict__ Mm, const int* __restrict__ tok,
    const float* __restrict__ Wcls, float* __restrict__ out)
{
    extern __shared__ float sm[];
    uint32_t* U_hi  = (uint32_t*)(sm + SM_UHI);
    uint32_t* U_lo  = (uint32_t*)(sm + SM_ULO);
    uint32_t* Vt_hi = (uint32_t*)(sm + SM_VTHI);
    uint32_t* Vt_lo = (uint32_t*)(sm + SM_VTLO);
    float*    hc_sb = sm + SM_HC;
    float*    mz_sb = sm + SM_MZ;
    int*      tok_s = (int*)(sm + SM_TOK);
    float*    mzs   = sm + SM_MZS;
    float*    red   = sm + SM_HC;   // alias: HC dead by the time red is used
    __shared__ int s_last;

    int t = blockIdx.x, b = blockIdx.y;
    int nit    = (t < 5) ? 4 : 3;                       // chunks this tile
    int c0     = (t < 5) ? 4 * t : 20 + 3 * (t - 5);    // first chunk index
    int pstart = c0 * 128;
    int tid = threadIdx.x, wid = tid >> 5, lane = tid & 31;
    int g = lane >> 2, tg = lane & 3;

    // ---- stage packed U (pairs over q), packed Vt (pairs over d), tok ----
    const float* Ub = U + (size_t)b * QQ * DD;
    for (int i = tid; i < 32 * DD; i += 256) {
        int pq = i >> 7, d = i & 127;
        uint32_t hi, lo;
        packsplit(Ub[(2 * pq) * DD + d], Ub[(2 * pq + 1) * DD + d], hi, lo);
        U_hi[pq * 136 + d] = hi; U_lo[pq * 136 + d] = lo;
    }
    const float* Vtb = g_Vt + (size_t)b * DD * QQ;
    for (int i = tid; i < 64 * QQ; i += 256) {
        int pd = i >> 6, q = i & 63;
        uint32_t hi, lo;
        packsplit(Vtb[(2 * pd) * QQ + q], Vtb[(2 * pd + 1) * QQ + q], hi, lo);
        Vt_hi[pd * 72 + q] = hi; Vt_lo[pd * 72 + q] = lo;
    }
    const int* tokb = tok + (size_t)b * PP + pstart;
    for (int i = tid; i < nit * 128; i += 256) tok_s[i] = tokb[i];
    __syncthreads();

    float* myhc = hc_sb + wid * 1088;   // 16 rows * 68 (half-width c2q bounce)
    float* mymz = mz_sb + wid * 32;

    // per-warp running partials (lane covers d = 4*lane + j)
    float pm_h[4], pm_c[4], pm_hc[4], pm_m[4], mnh[4], qacc[4];
#pragma unroll
    for (int j = 0; j < 4; j++) {
        pm_h[j] = NEGBIG; pm_c[j] = NEGBIG; pm_hc[j] = NEGBIG; pm_m[j] = NEGBIG;
        mnh[j] = POSBIG;  qacc[j] = 0.f;
    }
    float Mw = NEGBIG, Zw = 0.f;

    // loop-carried H A-fragment prefetch (covers it-boundary latency)
    const float* Hp0 = H + ((size_t)b * PP + pstart + wid * 16) * DD;
    float2 f0 = *(const float2*)(Hp0 + g * DD + 2 * tg);
    float2 f1 = *(const float2*)(Hp0 + (g + 8) * DD + 2 * tg);
    float2 f2 = *(const float2*)(Hp0 + g * DD + 8 + 2 * tg);
    float2 f3 = *(const float2*)(Hp0 + (g + 8) * DD + 8 + 2 * tg);

    for (int it = 0; it < nit; it++) {
        const float* Hp = Hp0 + (size_t)it * 128 * DD;
        const float* Mp = Mm + (Hp - H);

        // ---- S = H . Vt^T (3-term bf16 split) ----
        float sacc[8][4];
#pragma unroll
        for (int nt = 0; nt < 8; nt++)
            sacc[nt][0] = sacc[nt][1] = sacc[nt][2] = sacc[nt][3] = 0.f;

#pragma unroll
        for (int kt = 0; kt < 8; kt++) {
            uint32_t ah0, al0, ah1, al1, ah2, al2, ah3, al3;
            packsplit(f0.x, f0.y, ah0, al0);
            packsplit(f1.x, f1.y, ah1, al1);
            packsplit(f2.x, f2.y, ah2, al2);
            packsplit(f3.x, f3.y, ah3, al3);
            {   // prefetch: next kt, or next it's kt=0 (covered by c2q+pooling)
                const float* nxt = (kt < 7) ? (Hp + 16 * (kt + 1))
                                : ((it < nit - 1) ? (Hp + 128 * DD) : Hp);  // last it: dummy
                f0 = *(const float2*)(nxt + g * DD + 2 * tg);
                f1 = *(const float2*)(nxt + (g + 8) * DD + 2 * tg);
                f2 = *(const float2*)(nxt + g * DD + 8 + 2 * tg);
                f3 = *(const float2*)(nxt + (g + 8) * DD + 8 + 2 * tg);
            }
#pragma unroll
            for (int ch = 0; ch < 2; ch++) {
                uint32_t bh[4][2], bl[4][2];
#pragma unroll
                for (int j = 0; j < 4; j++) {
                    int c = 8 * (4 * ch + j) + g;
                    bh[j][0] = Vt_hi[(8 * kt + tg) * 72 + c];
                    bh[j][1] = Vt_hi[(8 * kt + tg + 4) * 72 + c];
                    bl[j][0] = Vt_lo[(8 * kt + tg) * 72 + c];
                    bl[j][1] = Vt_lo[(8 * kt + tg + 4) * 72 + c];
                }
#pragma unroll
                for (int j = 0; j < 4; j++)
                    mma_bf16(sacc[4 * ch + j], ah0, ah1, ah2, ah3, bh[j][0], bh[j][1]);
#pragma unroll
                for (int j = 0; j < 4; j++)
                    mma_bf16(sacc[4 * ch + j], ah0, ah1, ah2, ah3, bl[j][0], bl[j][1]);
#pragma unroll
                for (int j = 0; j < 4; j++)
                    mma_bf16(sacc[4 * ch + j], al0, al1, al2, al3, bh[j][0], bh[j][1]);
            }
        }

        // ---- softmax over q: rows g and g+8 ----
        float m0 = NEGBIG, m1 = NEGBIG;
#pragma unroll
        for (int nt = 0; nt < 8; nt++) {
            m0 = fmaxf(m0, fmaxf(sacc[nt][0], sacc[nt][1]));
            m1 = fmaxf(m1, fmaxf(sacc[nt][2], sacc[nt][3]));
        }
        m0 = fmaxf(m0, __shfl_xor_sync(0xffffffffu, m0, 1));
        m0 = fmaxf(m0, __shfl_xor_sync(0xffffffffu, m0, 2));
        m1 = fmaxf(m1, __shfl_xor_sync(0xffffffffu, m1, 1));
        m1 = fmaxf(m1, __shfl_xor_sync(0xffffffffu, m1, 2));

        float z0 = 0.f, z1 = 0.f;
#pragma unroll
        for (int nt = 0; nt < 8; nt++) {
            sacc[nt][0] = __expf(sacc[nt][0] - m0);
            sacc[nt][1] = __expf(sacc[nt][1] - m0);
            sacc[nt][2] = __expf(sacc[nt][2] - m1);
            sacc[nt][3] = __expf(sacc[nt][3] - m1);
            z0 += sacc[nt][0] + sacc[nt][1];
            z1 += sacc[nt][2] + sacc[nt][3];
        }
        z0 += __shfl_xor_sync(0xffffffffu, z0, 1);
        z0 += __shfl_xor_sync(0xffffffffu, z0, 2);
        z1 += __shfl_xor_sync(0xffffffffu, z1, 1);
        z1 += __shfl_xor_sync(0xffffffffu, z1, 2);

        if (tg == 0) {
            mymz[2 * g] = m0;           mymz[2 * g + 1] = z0;
            mymz[2 * (g + 8)] = m1;     mymz[2 * (g + 8) + 1] = z1;
        }

        // ---- pack e directly into c2q A-fragments (S C-frag == c2q A-frag) ----
        uint32_t ea_hi[4][4], ea_lo[4][4];
#pragma unroll
        for (int kt = 0; kt < 4; kt++) {
            packsplit(sacc[2 * kt][0],     sacc[2 * kt][1],     ea_hi[kt][0], ea_lo[kt][0]);
            packsplit(sacc[2 * kt][2],     sacc[2 * kt][3],     ea_hi[kt][1], ea_lo[kt][1]);
            packsplit(sacc[2 * kt + 1][0], sacc[2 * kt + 1][1], ea_hi[kt][2], ea_lo[kt][2]);
            packsplit(sacc[2 * kt + 1][2], sacc[2 * kt + 1][3], ea_hi[kt][3], ea_lo[kt][3]);
        }
        __syncwarp();   // mymz visible to all lanes

        // ---- per-iteration row statistics (shared by both halves) ----
        int rbase = (lane >> 4) * 8;    // this lane covers rows rbase..rbase+7
        float mloc = NEGBIG;
#pragma unroll
        for (int r = 0; r < 8; r++)
            mloc = fmaxf(mloc, mymz[2 * (rbase + r)]);
        float eev[8];
        float zloc = 0.f;
#pragma unroll
        for (int r = 0; r < 8; r++) {
            eev[r] = __expf(mymz[2 * (rbase + r)] - mloc);
            zloc += eev[r];
        }
        float mo  = __shfl_xor_sync(0xffffffffu, mloc, 16);
        float zo  = __shfl_xor_sync(0xffffffffu, zloc, 16);
        float m16 = fmaxf(mloc, mo);
        float e1  = __expf(mloc - m16);
        float e2  = __expf(mo - m16);
        float z16 = zloc * e1 + zo * e2;

        // ---- c2q in two d-column halves; all-lane pooling per half ----
#pragma unroll
        for (int half = 0; half < 2; half++) {
            float cacc[8][4];
#pragma unroll
            for (int ntl = 0; ntl < 8; ntl++)
                cacc[ntl][0] = cacc[ntl][1] = cacc[ntl][2] = cacc[ntl][3] = 0.f;

#pragma unroll
            for (int kt = 0; kt < 4; kt++) {
#pragma unroll
                for (int ch = 0; ch < 2; ch++) {
                    uint32_t bh[4][2], bl[4][2];
#pragma unroll
                    for (int j = 0; j < 4; j++) {
                        int c = 64 * half + 8 * (4 * ch + j) + g;
                        int r0i = (8 * kt + tg) * 136 + c;
                        int r1i = (8 * kt + tg + 4) * 136 + c;
                        bh[j][0] = U_hi[r0i]; bh[j][1] = U_hi[r1i];
                        bl[j][0] = U_lo[r0i]; bl[j][1] = U_lo[r1i];
                    }
#pragma unroll
                    for (int j = 0; j < 4; j++)
                        mma_bf16(cacc[4 * ch + j], ea_hi[kt][0], ea_hi[kt][1], ea_hi[kt][2], ea_hi[kt][3], bh[j][0], bh[j][1]);
#pragma unroll
                    for (int j = 0; j < 4; j++)
                        mma_bf16(cacc[4 * ch + j], ea_hi[kt][0], ea_hi[kt][1], ea_hi[kt][2], ea_hi[kt][3], bl[j][0], bl[j][1]);
#pragma unroll
                    for (int j = 0; j < 4; j++)
                        mma_bf16(cacc[4 * ch + j], ea_lo[kt][0], ea_lo[kt][1], ea_lo[kt][2], ea_lo[kt][3], bh[j][0], bh[j][1]);
                }
            }
            __syncwarp();   // previous half's pooling reads done
#pragma unroll
            for (int ntl = 0; ntl < 8; ntl++) {
                *(float2*)(myhc + g * 68 + 8 * ntl + 2 * tg)       = make_float2(cacc[ntl][0], cacc[ntl][1]);
                *(float2*)(myhc + (g + 8) * 68 + 8 * ntl + 2 * tg) = make_float2(cacc[ntl][2], cacc[ntl][3]);
            }
            __syncwarp();

            // ---- all-lane pooling: pair (l, l^16) splits 16 rows ----
            {
                int aq   = lane & 15;           // quad within this half
                int gcol = 64 * half + 4 * aq;  // global d column

                float s_h[4], s_c[4], s_hc[4], s_m[4], s_n[4], s_q[4];
#pragma unroll
                for (int j = 0; j < 4; j++) {
                    s_h[j] = NEGBIG; s_c[j] = NEGBIG; s_hc[j] = NEGBIG;
                    s_m[j] = NEGBIG; s_n[j] = POSBIG; s_q[j] = 0.f;
                }

#pragma unroll
                for (int r = 0; r < 8; r++) {
                    int row = rbase + r;
                    float invz = 1.0f / mymz[2 * row + 1];
                    float4 c4 = *(float4*)(myhc + row * 68 + 4 * aq);
                    float4 h4 = *(const float4*)(Hp + row * DD + gcol);
                    float4 m4 = *(const float4*)(Mp + row * DD + gcol);  // unconditional (MLP)
                    float cv[4] = {c4.x * invz, c4.y * invz, c4.z * invz, c4.w * invz};
                    float hv[4] = {h4.x, h4.y, h4.z, h4.w};
                    float mv[4] = {m4.x, m4.y, m4.z, m4.w};

                    float ee = eev[r];
#pragma unroll
                    for (int j = 0; j < 4; j++) s_q[j] += ee * hv[j];

                    if (tok_s[it * 128 + wid * 16 + row] != 0) {   // warp-uniform branch
#pragma unroll
                        for (int j = 0; j < 4; j++) {
                            s_h[j]  = fmaxf(s_h[j],  hv[j]);
                            s_c[j]  = fmaxf(s_c[j],  cv[j]);
                            s_hc[j] = fmaxf(s_hc[j], hv[j] * cv[j]);
                            s_m[j]  = fmaxf(s_m[j],  mv[j]);
                            s_n[j]  = fminf(s_n[j],  hv[j]);
                        }
                    }
                }

                // pair merge (both lanes get merged values)
#pragma unroll
                for (int j = 0; j < 4; j++) {
                    s_h[j]  = fmaxf(s_h[j],  __shfl_xor_sync(0xffffffffu, s_h[j],  16));
                    s_c[j]  = fmaxf(s_c[j],  __shfl_xor_sync(0xffffffffu, s_c[j],  16));
                    s_hc[j] = fmaxf(s_hc[j], __shfl_xor_sync(0xffffffffu, s_hc[j], 16));
                    s_m[j]  = fmaxf(s_m[j],  __shfl_xor_sync(0xffffffffu, s_m[j],  16));
                    s_n[j]  = fminf(s_n[j],  __shfl_xor_sync(0xffffffffu, s_n[j],  16));
                }
                float qo[4];
#pragma unroll
                for (int j = 0; j < 4; j++) qo[j] = __shfl_xor_sync(0xffffffffu, s_q[j], 16);
#pragma unroll
                for (int j = 0; j < 4; j++) s_q[j] = s_q[j] * e1 + qo[j] * e2;

                // owner lane folds into persistent partials (its own quad)
                if ((lane >> 4) == half) {
                    float nM = fmaxf(Mw, m16);
                    float aa = __expf(Mw - nM);
                    float ee = __expf(m16 - nM);
#pragma unroll
                    for (int j = 0; j < 4; j++) qacc[j] = qacc[j] * aa + s_q[j] * ee;
                    Zw = Zw * aa + z16 * ee;
                    Mw = nM;
#pragma unroll
                    for (int j = 0; j < 4; j++) {
                        pm_h[j]  = fmaxf(pm_h[j],  s_h[j]);
                        pm_c[j]  = fmaxf(pm_c[j],  s_c[j]);
                        pm_hc[j] = fmaxf(pm_hc[j], s_hc[j]);
                        pm_m[j]  = fmaxf(pm_m[j],  s_m[j]);
                        mnh[j]   = fminf(mnh[j],   s_n[j]);
                    }
                }
            }
            __syncwarp();
        }
    }

    // ---------------- block reduction -> tile partials ----------------
    __syncthreads();
    if (lane == 0) { mzs[wid * 2] = Mw; mzs[wid * 2 + 1] = Zw; }
    __syncthreads();
    float Mb = mzs[0];
#pragma unroll
    for (int w = 1; w < 8; w++) Mb = fmaxf(Mb, mzs[2 * w]);

    float* pout = g_part + ((size_t)b * NT + t) * 1024;
    float sc = __expf(Mw - Mb);

    *(float4*)(red + wid * DD + 4 * lane) =
        make_float4(qacc[0] * sc, qacc[1] * sc, qacc[2] * sc, qacc[3] * sc);
    __syncthreads();
    if (tid < DD) {
        float r = 0.f;
#pragma unroll
        for (int w = 0; w < 8; w++) r += red[w * DD + tid];
        pout[tid] = r;
    }

#define BLK_MAXRED(arr, off)                                                   \
    do {                                                                       \
        __syncthreads();                                                       \
        *(float4*)(red + wid * DD + 4 * lane) =                                \
            make_float4((arr)[0], (arr)[1], (arr)[2], (arr)[3]);               \
        __syncthreads();                                                       \
        if (tid < DD) {                                                        \
            float r = red[tid];                                                \
            for (int w = 1; w < 8; w++) r = fmaxf(r, red[w * DD + tid]);       \
            pout[(off) + tid] = r;                                             \
        }                                                                      \
    } while (0)

    BLK_MAXRED(pm_h, 128);
    BLK_MAXRED(pm_c, 256);
    BLK_MAXRED(pm_hc, 384);
    BLK_MAXRED(pm_m, 512);

    __syncthreads();
    *(float4*)(red + wid * DD + 4 * lane) = make_float4(mnh[0], mnh[1], mnh[2], mnh[3]);
    __syncthreads();
    if (tid < DD) {
        float r = red[tid];
#pragma unroll
        for (int w = 1; w < 8; w++) r = fminf(r, red[w * DD + tid]);
        pout[768 + tid] = r;
    }
    if (tid == 0) {
        float Zt = 0.f;
#pragma unroll
        for (int w = 0; w < 8; w++) Zt += mzs[2 * w + 1] * __expf(mzs[2 * w] - Mb);
        pout[896] = Mb;
        pout[897] = Zt;
    }

    // ---------------- fused finalize: last block of batch b ----------------
    __syncthreads();
    __threadfence();
    if (tid == 0) s_last = (atomicAdd(&g_cnt[b], 1) == NT - 1) ? 1 : 0;
    __syncthreads();
    if (s_last) {
        __threadfence();
        float o0 = 0.f, o1 = 0.f;
        if (tid < DD) {
            int d = tid;
            const float* base = g_part + (size_t)b * NT * 1024;
            float Mg = NEGBIG;
#pragma unroll
            for (int tt = 0; tt < NT; tt++) Mg = fmaxf(Mg, base[tt * 1024 + 896]);
            float Z = 0.f, qa = 0.f;
            float ph = NEGBIG, pc = NEGBIG, phc = NEGBIG, pmx = NEGBIG, nh = POSBIG;
#pragma unroll
            for (int tt = 0; tt < NT; tt++) {
                const float* pt = base + tt * 1024;
                float scv = __expf(pt[896] - Mg);
                Z  += pt[897] * scv;
                qa += pt[d] * scv;
                ph  = fmaxf(ph,  pt[128 + d]);
                pc  = fmaxf(pc,  pt[256 + d]);
                phc = fmaxf(phc, pt[384 + d]);
                pmx = fmaxf(pmx, pt[512 + d]);
                nh  = fminf(nh,  pt[768 + d]);
            }
            float q2c = qa / Z;
            float phq = fmaxf(q2c * ph, q2c * nh);   // ph == masked max of H
            o0 = ph * Wcls[2 * d] + pc * Wcls[2 * (128 + d)] + phc * Wcls[2 * (256 + d)]
               + phq * Wcls[2 * (384 + d)] + pmx * Wcls[2 * (512 + d)];
            o1 = ph * Wcls[2 * d + 1] + pc * Wcls[2 * (128 + d) + 1] + phc * Wcls[2 * (256 + d) + 1]
               + phq * Wcls[2 * (384 + d) + 1] + pmx * Wcls[2 * (512 + d) + 1];
        }
        __syncthreads();
        float* r0 = red;
        float* r1 = red + 128;
        if (tid < DD) { r0[tid] = o0; r1[tid] = o1; }
        __syncthreads();
        for (int s = 64; s > 0; s >>= 1) {
            if (tid < s) { r0[tid] += r0[tid + s]; r1[tid] += r1[tid + s]; }
            __syncthreads();
        }
        if (tid == 0) {
            out[b * 2]     = r0[0];
            out[b * 2 + 1] = r1[0];
            g_cnt[b] = 0;   // reset for next graph replay
        }
    }
}

// ---------------------------------------------------------------------------
extern "C" void kernel_launch(void* const* d_in, const int* in_sizes, int n_in,
                              void* d_out, int out_size) {
    const float* H     = (const float*)d_in[0];
    const float* U     = (const float*)d_in[1];
    const float* Mm    = (const float*)d_in[2];
    const int*   tok   = (const int*)d_in[3];    // int32 on the wire
    const float* Wattn = (const float*)d_in[4];
    const float* Wcls  = (const float*)d_in[5];
    float*       out   = (float*)d_out;

    cudaFuncSetAttribute(main_kernel, cudaFuncAttributeMaxDynamicSharedMemorySize, SMEM_BYTES);

    vt_kernel<<<dim3(8, BB), 256>>>(U, Wattn);
    main_kernel<<<dim3(NT, BB), 256, SMEM_BYTES>>>(H, U, Mm, tok, Wcls, out);
}

// round 15
// speedup vs baseline: 1.1304x; 1.1304x over previous
#include <cuda_runtime.h>
#include <cuda_bf16.h>
#include <cstdint>

#define BB 32
#define PP 4096
#define QQ 64
#define DD 128
#define NT 9
#define NEGBIG (-1e30f)
#define POSBIG (1e30f)

// ---- main kernel smem layout (32-bit words) ----
#define SM_UHI   0        // U hi packed  [qp*136 + d]   32*136 = 4352
#define SM_ULO   4352     // U lo packed                  4352
#define SM_VTHI  8704     // Vt hi packed [dp*72 + q]    64*72  = 4608
#define SM_VTLO  13312    // Vt lo packed                 4608
#define SM_HC    17920    // per warp c2q half buffer 16*68 = 1088; 8*1088 = 8704
#define SM_MZ    26624    // per warp row (m,z) 16*2      8*32 = 256
#define SM_TOK   26880    // tok ints                     512
#define SM_MZS   27392    // warp M/Z                     16
#define SM_EEV   27408    // per warp eev[16]             8*16 = 128
#define SM_TOTAL 27536
#define SMEM_BYTES (SM_TOTAL * 4)

// device scratch (zero-initialized)
__device__ float g_Vt[BB * DD * QQ];      // Vt[b][d][q]
__device__ float g_part[BB * NT * 1024];  // per (b,tile) partials
__device__ int   g_cnt[BB];               // arrival counters (left 0 after each call)

// ---------------------------------------------------------------------------
__device__ __forceinline__ void mma_bf16(float* d,
    uint32_t a0, uint32_t a1, uint32_t a2, uint32_t a3,
    uint32_t b0, uint32_t b1)
{
    asm volatile(
        "mma.sync.aligned.m16n8k16.row.col.f32.bf16.bf16.f32 "
        "{%0,%1,%2,%3}, {%4,%5,%6,%7}, {%8,%9}, {%0,%1,%2,%3};"
        : "+f"(d[0]), "+f"(d[1]), "+f"(d[2]), "+f"(d[3])
        : "r"(a0), "r"(a1), "r"(a2), "r"(a3), "r"(b0), "r"(b1));
}

// split (x0,x1) into packed bf16x2 hi and lo (x = hi + lo + O(2^-17 x))
__device__ __forceinline__ void packsplit(float x0, float x1, uint32_t& hi, uint32_t& lo) {
    __nv_bfloat162 h = __float22bfloat162_rn(make_float2(x0, x1));
    float2 hf = __bfloat1622float2(h);
    __nv_bfloat162 l = __float22bfloat162_rn(make_float2(x0 - hf.x, x1 - hf.y));
    hi = *reinterpret_cast<uint32_t*>(&h);
    lo = *reinterpret_cast<uint32_t*>(&l);
}

// ---------------------------------------------------------------------------
// Kernel 1: Vt[b][d][q] = sum_e W[d,e]*U[b,q,e] (fp32 exact). grid (8,32).
// ---------------------------------------------------------------------------
__global__ void vt_kernel(const float* __restrict__ U, const float* __restrict__ W) {
    __shared__ float U_s[QQ * 129];
    __shared__ float W_s[16 * DD];
    int b = blockIdx.y, dbase = blockIdx.x * 16, tid = threadIdx.x;

    const float* Ub = U + (size_t)b * QQ * DD;
    for (int i = tid; i < QQ * DD; i += 256)
        U_s[(i >> 7) * 129 + (i & 127)] = Ub[i];
    for (int i = tid; i < 16 * DD; i += 256)
        W_s[i] = W[(size_t)dbase * DD + i];
    __syncthreads();

    int q = tid & 63, dg = tid >> 6;
    float acc[4] = {0.f, 0.f, 0.f, 0.f};
#pragma unroll 4
    for (int e = 0; e < DD; e++) {
        float u = U_s[q * 129 + e];
#pragma unroll
        for (int k = 0; k < 4; k++)
            acc[k] += u * W_s[(dg * 4 + k) * DD + e];
    }
#pragma unroll
    for (int k = 0; k < 4; k++)
        g_Vt[((size_t)b * DD + dbase + dg * 4 + k) * QQ + q] = acc[k];
}

// ---------------------------------------------------------------------------
// Kernel 2: fused attention (bf16-split MMA) + pooling + fused finalize.
// grid (NT=9, 32), 256 threads, 2 CTAs/SM. Tiles 0-4: 4 chunks; 5-8: 3 chunks.
// ---------------------------------------------------------------------------
__global__ void __launch_bounds__(256, 2) main_kernel(
    const float* __restrict__ H, const float* __restrict__ U,
    const float* __restrict__ Mm, const int* __restrict__ tok,
    const float* __restrict__ Wcls, float* __restrict__ out)
{
    extern __shared__ float sm[];
    uint32_t* U_hi  = (uint32_t*)(sm + SM_UHI);
    uint32_t* U_lo  = (uint32_t*)(sm + SM_ULO);
    uint32_t* Vt_hi = (uint32_t*)(sm + SM_VTHI);
    uint32_t* Vt_lo = (uint32_t*)(sm + SM_VTLO);
    float*    hc_sb = sm + SM_HC;
    float*    mz_sb = sm + SM_MZ;
    int*      tok_s = (int*)(sm + SM_TOK);
    float*    mzs   = sm + SM_MZS;
    float*    eev_sb = sm + SM_EEV;
    float*    red   = sm + SM_HC;   // alias: HC dead by the time red is used
    __shared__ int s_last;

    int t = blockIdx.x, b = blockIdx.y;
    int nit    = (t < 5) ? 4 : 3;                       // chunks this tile
    int c0     = (t < 5) ? 4 * t : 20 + 3 * (t - 5);    // first chunk index
    int pstart = c0 * 128;
    int tid = threadIdx.x, wid = tid >> 5, lane = tid & 31;
    int g = lane >> 2, tg = lane & 3;

    // ---- stage packed U (pairs over q), packed Vt (pairs over d), tok ----
    const float* Ub = U + (size_t)b * QQ * DD;
    for (int i = tid; i < 32 * DD; i += 256) {
        int pq = i >> 7, d = i & 127;
        uint32_t hi, lo;
        packsplit(Ub[(2 * pq) * DD + d], Ub[(2 * pq + 1) * DD + d], hi, lo);
        U_hi[pq * 136 + d] = hi; U_lo[pq * 136 + d] = lo;
    }
    const float* Vtb = g_Vt + (size_t)b * DD * QQ;
    for (int i = tid; i < 64 * QQ; i += 256) {
        int pd = i >> 6, q = i & 63;
        uint32_t hi, lo;
        packsplit(Vtb[(2 * pd) * QQ + q], Vtb[(2 * pd + 1) * QQ + q], hi, lo);
        Vt_hi[pd * 72 + q] = hi; Vt_lo[pd * 72 + q] = lo;
    }
    const int* tokb = tok + (size_t)b * PP + pstart;
    for (int i = tid; i < nit * 128; i += 256) tok_s[i] = tokb[i];
    __syncthreads();

    float* myhc = hc_sb + wid * 1088;   // 16 rows * 68 (half-width c2q bounce)
    float* mymz = mz_sb + wid * 32;
    float* myee = eev_sb + wid * 16;

    // per-warp running partials (lane covers d = 4*lane + j)
    float pm_h[4], pm_c[4], pm_hc[4], pm_m[4], mnh[4], qacc[4];
#pragma unroll
    for (int j = 0; j < 4; j++) {
        pm_h[j] = NEGBIG; pm_c[j] = NEGBIG; pm_hc[j] = NEGBIG; pm_m[j] = NEGBIG;
        mnh[j] = POSBIG;  qacc[j] = 0.f;
    }
    float Mw = NEGBIG, Zw = 0.f;

    // loop-carried H A-fragment prefetch (covers it-boundary latency)
    const float* Hp0 = H + ((size_t)b * PP + pstart + wid * 16) * DD;
    float2 f0 = *(const float2*)(Hp0 + g * DD + 2 * tg);
    float2 f1 = *(const float2*)(Hp0 + (g + 8) * DD + 2 * tg);
    float2 f2 = *(const float2*)(Hp0 + g * DD + 8 + 2 * tg);
    float2 f3 = *(const float2*)(Hp0 + (g + 8) * DD + 8 + 2 * tg);

    for (int it = 0; it < nit; it++) {
        const float* Hp = Hp0 + (size_t)it * 128 * DD;
        const float* Mp = Mm + (Hp - H);

        // ---- S = H . Vt^T (3-term bf16 split) ----
        float sacc[8][4];
#pragma unroll
        for (int nt = 0; nt < 8; nt++)
            sacc[nt][0] = sacc[nt][1] = sacc[nt][2] = sacc[nt][3] = 0.f;

#pragma unroll
        for (int kt = 0; kt < 8; kt++) {
            uint32_t ah0, al0, ah1, al1, ah2, al2, ah3, al3;
            packsplit(f0.x, f0.y, ah0, al0);
            packsplit(f1.x, f1.y, ah1, al1);
            packsplit(f2.x, f2.y, ah2, al2);
            packsplit(f3.x, f3.y, ah3, al3);
            {   // prefetch: next kt, or next it's kt=0 (covered by c2q+pooling)
                const float* nxt = (kt < 7) ? (Hp + 16 * (kt + 1))
                                : ((it < nit - 1) ? (Hp + 128 * DD) : Hp);  // last it: dummy
                f0 = *(const float2*)(nxt + g * DD + 2 * tg);
                f1 = *(const float2*)(nxt + (g + 8) * DD + 2 * tg);
                f2 = *(const float2*)(nxt + g * DD + 8 + 2 * tg);
                f3 = *(const float2*)(nxt + (g + 8) * DD + 8 + 2 * tg);
            }
#pragma unroll
            for (int ch = 0; ch < 2; ch++) {
                uint32_t bh[4][2], bl[4][2];
#pragma unroll
                for (int j = 0; j < 4; j++) {
                    int c = 8 * (4 * ch + j) + g;
                    bh[j][0] = Vt_hi[(8 * kt + tg) * 72 + c];
                    bh[j][1] = Vt_hi[(8 * kt + tg + 4) * 72 + c];
                    bl[j][0] = Vt_lo[(8 * kt + tg) * 72 + c];
                    bl[j][1] = Vt_lo[(8 * kt + tg + 4) * 72 + c];
                }
#pragma unroll
                for (int j = 0; j < 4; j++)
                    mma_bf16(sacc[4 * ch + j], ah0, ah1, ah2, ah3, bh[j][0], bh[j][1]);
#pragma unroll
                for (int j = 0; j < 4; j++)
                    mma_bf16(sacc[4 * ch + j], ah0, ah1, ah2, ah3, bl[j][0], bl[j][1]);
#pragma unroll
                for (int j = 0; j < 4; j++)
                    mma_bf16(sacc[4 * ch + j], al0, al1, al2, al3, bh[j][0], bh[j][1]);
            }
        }

        // ---- softmax over q: rows g and g+8 ----
        float m0 = NEGBIG, m1 = NEGBIG;
#pragma unroll
        for (int nt = 0; nt < 8; nt++) {
            m0 = fmaxf(m0, fmaxf(sacc[nt][0], sacc[nt][1]));
            m1 = fmaxf(m1, fmaxf(sacc[nt][2], sacc[nt][3]));
        }
        m0 = fmaxf(m0, __shfl_xor_sync(0xffffffffu, m0, 1));
        m0 = fmaxf(m0, __shfl_xor_sync(0xffffffffu, m0, 2));
        m1 = fmaxf(m1, __shfl_xor_sync(0xffffffffu, m1, 1));
        m1 = fmaxf(m1, __shfl_xor_sync(0xffffffffu, m1, 2));

        float z0 = 0.f, z1 = 0.f;
#pragma unroll
        for (int nt = 0; nt < 8; nt++) {
            sacc[nt][0] = __expf(sacc[nt][0] - m0);
            sacc[nt][1] = __expf(sacc[nt][1] - m0);
            sacc[nt][2] = __expf(sacc[nt][2] - m1);
            sacc[nt][3] = __expf(sacc[nt][3] - m1);
            z0 += sacc[nt][0] + sacc[nt][1];
            z1 += sacc[nt][2] + sacc[nt][3];
        }
        z0 += __shfl_xor_sync(0xffffffffu, z0, 1);
        z0 += __shfl_xor_sync(0xffffffffu, z0, 2);
        z1 += __shfl_xor_sync(0xffffffffu, z1, 1);
        z1 += __shfl_xor_sync(0xffffffffu, z1, 2);

        if (tg == 0) {
            mymz[2 * g] = m0;           mymz[2 * g + 1] = z0;
            mymz[2 * (g + 8)] = m1;     mymz[2 * (g + 8) + 1] = z1;
        }

        // ---- pack e directly into c2q A-fragments (S C-frag == c2q A-frag) ----
        uint32_t ea_hi[4][4], ea_lo[4][4];
#pragma unroll
        for (int kt = 0; kt < 4; kt++) {
            packsplit(sacc[2 * kt][0],     sacc[2 * kt][1],     ea_hi[kt][0], ea_lo[kt][0]);
            packsplit(sacc[2 * kt][2],     sacc[2 * kt][3],     ea_hi[kt][1], ea_lo[kt][1]);
            packsplit(sacc[2 * kt + 1][0], sacc[2 * kt + 1][1], ea_hi[kt][2], ea_lo[kt][2]);
            packsplit(sacc[2 * kt + 1][2], sacc[2 * kt + 1][3], ea_hi[kt][3], ea_lo[kt][3]);
        }
        __syncwarp();   // mymz visible to all lanes

        // ---- per-iteration row stats, computed ONCE; eev parked in smem ----
        int rbase = (lane >> 4) * 8;    // this lane covers rows rbase..rbase+7
        float m16, z16, e1, e2;
        {
            float mloc = NEGBIG;
#pragma unroll
            for (int r = 0; r < 8; r++)
                mloc = fmaxf(mloc, mymz[2 * (rbase + r)]);
            float zloc = 0.f;
#pragma unroll
            for (int r = 0; r < 8; r++) {
                float e = __expf(mymz[2 * (rbase + r)] - mloc);
                zloc += e;
                if ((lane & 15) == 0) myee[rbase + r] = e;   // lanes 0,16 write
            }
            float mo = __shfl_xor_sync(0xffffffffu, mloc, 16);
            float zo = __shfl_xor_sync(0xffffffffu, zloc, 16);
            m16 = fmaxf(mloc, mo);
            e1  = __expf(mloc - m16);
            e2  = __expf(mo - m16);
            z16 = zloc * e1 + zo * e2;
        }
        __syncwarp();

        // ---- c2q in two d-column halves; all-lane pooling per half ----
#pragma unroll
        for (int half = 0; half < 2; half++) {
            float cacc[8][4];
#pragma unroll
            for (int ntl = 0; ntl < 8; ntl++)
                cacc[ntl][0] = cacc[ntl][1] = cacc[ntl][2] = cacc[ntl][3] = 0.f;

#pragma unroll
            for (int kt = 0; kt < 4; kt++) {
#pragma unroll
                for (int ch = 0; ch < 2; ch++) {
                    uint32_t bh[4][2], bl[4][2];
#pragma unroll
                    for (int j = 0; j < 4; j++) {
                        int c = 64 * half + 8 * (4 * ch + j) + g;
                        int r0i = (8 * kt + tg) * 136 + c;
                        int r1i = (8 * kt + tg + 4) * 136 + c;
                        bh[j][0] = U_hi[r0i]; bh[j][1] = U_hi[r1i];
                        bl[j][0] = U_lo[r0i]; bl[j][1] = U_lo[r1i];
                    }
#pragma unroll
                    for (int j = 0; j < 4; j++)
                        mma_bf16(cacc[4 * ch + j], ea_hi[kt][0], ea_hi[kt][1], ea_hi[kt][2], ea_hi[kt][3], bh[j][0], bh[j][1]);
#pragma unroll
                    for (int j = 0; j < 4; j++)
                        mma_bf16(cacc[4 * ch + j], ea_hi[kt][0], ea_hi[kt][1], ea_hi[kt][2], ea_hi[kt][3], bl[j][0], bl[j][1]);
#pragma unroll
                    for (int j = 0; j < 4; j++)
                        mma_bf16(cacc[4 * ch + j], ea_lo[kt][0], ea_lo[kt][1], ea_lo[kt][2], ea_lo[kt][3], bh[j][0], bh[j][1]);
                }
            }
            __syncwarp();   // previous half's pooling reads done
#pragma unroll
            for (int ntl = 0; ntl < 8; ntl++) {
                *(float2*)(myhc + g * 68 + 8 * ntl + 2 * tg)       = make_float2(cacc[ntl][0], cacc[ntl][1]);
                *(float2*)(myhc + (g + 8) * 68 + 8 * ntl + 2 * tg) = make_float2(cacc[ntl][2], cacc[ntl][3]);
            }
            __syncwarp();

            // ---- all-lane pooling: pair (l, l^16) splits the 16 rows ----
            {
                int aq   = lane & 15;           // quad within this half
                int gcol = 64 * half + 4 * aq;  // global d column

                float s_h[4], s_c[4], s_hc[4], s_m[4], s_n[4], s_q[4];
#pragma unroll
                for (int j = 0; j < 4; j++) {
                    s_h[j] = NEGBIG; s_c[j] = NEGBIG; s_hc[j] = NEGBIG;
                    s_m[j] = NEGBIG; s_n[j] = POSBIG; s_q[j] = 0.f;
                }

#pragma unroll 4
                for (int r = 0; r < 8; r++) {
                    int row = rbase + r;
                    float invz = 1.0f / mymz[2 * row + 1];
                    float4 c4 = *(float4*)(myhc + row * 68 + 4 * aq);
                    float4 h4 = *(const float4*)(Hp + row * DD + gcol);
                    float4 m4 = *(const float4*)(Mp + row * DD + gcol);  // unconditional (MLP)
                    float cv[4] = {c4.x * invz, c4.y * invz, c4.z * invz, c4.w * invz};
                    float hv[4] = {h4.x, h4.y, h4.z, h4.w};
                    float mv[4] = {m4.x, m4.y, m4.z, m4.w};

                    float ee = myee[row];
#pragma unroll
                    for (int j = 0; j < 4; j++) s_q[j] += ee * hv[j];

                    bool v = (tok_s[it * 128 + wid * 16 + row] != 0);
#pragma unroll
                    for (int j = 0; j < 4; j++) {   // predicated, no branch
                        s_h[j]  = fmaxf(s_h[j],  v ? hv[j]        : NEGBIG);
                        s_c[j]  = fmaxf(s_c[j],  v ? cv[j]        : NEGBIG);
                        s_hc[j] = fmaxf(s_hc[j], v ? hv[j]*cv[j]  : NEGBIG);
                        s_m[j]  = fmaxf(s_m[j],  v ? mv[j]        : NEGBIG);
                        s_n[j]  = fminf(s_n[j],  v ? hv[j]        : POSBIG);
                    }
                }

                // pair merge (both lanes get merged values)
#pragma unroll
                for (int j = 0; j < 4; j++) {
                    s_h[j]  = fmaxf(s_h[j],  __shfl_xor_sync(0xffffffffu, s_h[j],  16));
                    s_c[j]  = fmaxf(s_c[j],  __shfl_xor_sync(0xffffffffu, s_c[j],  16));
                    s_hc[j] = fmaxf(s_hc[j], __shfl_xor_sync(0xffffffffu, s_hc[j], 16));
                    s_m[j]  = fmaxf(s_m[j],  __shfl_xor_sync(0xffffffffu, s_m[j],  16));
                    s_n[j]  = fminf(s_n[j],  __shfl_xor_sync(0xffffffffu, s_n[j],  16));
                }
                float qo[4];
#pragma unroll
                for (int j = 0; j < 4; j++) qo[j] = __shfl_xor_sync(0xffffffffu, s_q[j], 16);
#pragma unroll
                for (int j = 0; j < 4; j++) s_q[j] = s_q[j] * e1 + qo[j] * e2;

                // owner lane folds into persistent partials (its own quad)
                if ((lane >> 4) == half) {
                    float nM = fmaxf(Mw, m16);
                    float aa = __expf(Mw - nM);
                    float ee = __expf(m16 - nM);
#pragma unroll
                    for (int j = 0; j < 4; j++) qacc[j] = qacc[j] * aa + s_q[j] * ee;
                    Zw = Zw * aa + z16 * ee;
                    Mw = nM;
#pragma unroll
                    for (int j = 0; j < 4; j++) {
                        pm_h[j]  = fmaxf(pm_h[j],  s_h[j]);
                        pm_c[j]  = fmaxf(pm_c[j],  s_c[j]);
                        pm_hc[j] = fmaxf(pm_hc[j], s_hc[j]);
                        pm_m[j]  = fmaxf(pm_m[j],  s_m[j]);
                        mnh[j]   = fminf(mnh[j],   s_n[j]);
                    }
                }
            }
            __syncwarp();
        }
    }

    // ---------------- block reduction -> tile partials ----------------
    __syncthreads();
    if (lane == 0) { mzs[wid * 2] = Mw; mzs[wid * 2 + 1] = Zw; }
    __syncthreads();
    float Mb = mzs[0];
#pragma unroll
    for (int w = 1; w < 8; w++) Mb = fmaxf(Mb, mzs[2 * w]);

    float* pout = g_part + ((size_t)b * NT + t) * 1024;
    float sc = __expf(Mw - Mb);

    *(float4*)(red + wid * DD + 4 * lane) =
        make_float4(qacc[0] * sc, qacc[1] * sc, qacc[2] * sc, qacc[3] * sc);
    __syncthreads();
    if (tid < DD) {
        float r = 0.f;
#pragma unroll
        for (int w = 0; w < 8; w++) r += red[w * DD + tid];
        pout[tid] = r;
    }

#define BLK_MAXRED(arr, off)                                                   \
    do {                                                                       \
        __syncthreads();                                                       \
        *(float4*)(red + wid * DD + 4 * lane) =                                \
            make_float4((arr)[0], (arr)[1], (arr)[2], (arr)[3]);               \
        __syncthreads();                                                       \
        if (tid < DD) {                                                        \
            float r = red[tid];                                                \
            for (int w = 1; w < 8; w++) r = fmaxf(r, red[w * DD + tid]);       \
            pout[(off) + tid] = r;                                             \
        }                                                                      \
    } while (0)

    BLK_MAXRED(pm_h, 128);
    BLK_MAXRED(pm_c, 256);
    BLK_MAXRED(pm_hc, 384);
    BLK_MAXRED(pm_m, 512);

    __syncthreads();
    *(float4*)(red + wid * DD + 4 * lane) = make_float4(mnh[0], mnh[1], mnh[2], mnh[3]);
    __syncthreads();
    if (tid < DD) {
        float r = red[tid];
#pragma unroll
        for (int w = 1; w < 8; w++) r = fminf(r, red[w * DD + tid]);
        pout[768 + tid] = r;
    }
    if (tid == 0) {
        float Zt = 0.f;
#pragma unroll
        for (int w = 0; w < 8; w++) Zt += mzs[2 * w + 1] * __expf(mzs[2 * w] - Mb);
        pout[896] = Mb;
        pout[897] = Zt;
    }

    // ---------------- fused finalize: last block of batch b ----------------
    __syncthreads();
    __threadfence();
    if (tid == 0) s_last = (atomicAdd(&g_cnt[b], 1) == NT - 1) ? 1 : 0;
    __syncthreads();
    if (s_last) {
        __threadfence();
        float o0 = 0.f, o1 = 0.f;
        if (tid < DD) {
            int d = tid;
            const float* base = g_part + (size_t)b * NT * 1024;
            float Mg = NEGBIG;
#pragma unroll
            for (int tt = 0; tt < NT; tt++) Mg = fmaxf(Mg, base[tt * 1024 + 896]);
            float Z = 0.f, qa = 0.f;
            float ph = NEGBIG, pc = NEGBIG, phc = NEGBIG, pmx = NEGBIG, nh = POSBIG;
#pragma unroll
            for (int tt = 0; tt < NT; tt++) {
                const float* pt = base + tt * 1024;
                float scv = __expf(pt[896] - Mg);
                Z  += pt[897] * scv;
                qa += pt[d] * scv;
                ph  = fmaxf(ph,  pt[128 + d]);
                pc  = fmaxf(pc,  pt[256 + d]);
                phc = fmaxf(phc, pt[384 + d]);
                pmx = fmaxf(pmx, pt[512 + d]);
                nh  = fminf(nh,  pt[768 + d]);
            }
            float q2c = qa / Z;
            float phq = fmaxf(q2c * ph, q2c * nh);   // ph == masked max of H
            o0 = ph * Wcls[2 * d] + pc * Wcls[2 * (128 + d)] + phc * Wcls[2 * (256 + d)]
               + phq * Wcls[2 * (384 + d)] + pmx * Wcls[2 * (512 + d)];
            o1 = ph * Wcls[2 * d + 1] + pc * Wcls[2 * (128 + d) + 1] + phc * Wcls[2 * (256 + d) + 1]
               + phq * Wcls[2 * (384 + d) + 1] + pmx * Wcls[2 * (512 + d) + 1];
        }
        __syncthreads();
        float* r0 = red;
        float* r1 = red + 128;
        if (tid < DD) { r0[tid] = o0; r1[tid] = o1; }
        __syncthreads();
        for (int s = 64; s > 0; s >>= 1) {
            if (tid < s) { r0[tid] += r0[tid + s]; r1[tid] += r1[tid + s]; }
            __syncthreads();
        }
        if (tid == 0) {
            out[b * 2]     = r0[0];
            out[b * 2 + 1] = r1[0];
            g_cnt[b] = 0;   // reset for next graph replay
        }
    }
}

// ---------------------------------------------------------------------------
extern "C" void kernel_launch(void* const* d_in, const int* in_sizes, int n_in,
                              void* d_out, int out_size) {
    const float* H     = (const float*)d_in[0];
    const float* U     = (const float*)d_in[1];
    const float* Mm    = (const float*)d_in[2];
    const int*   tok   = (const int*)d_in[3];    // int32 on the wire
    const float* Wattn = (const float*)d_in[4];
    const float* Wcls  = (const float*)d_in[5];
    float*       out   = (float*)d_out;

    cudaFuncSetAttribute(main_kernel, cudaFuncAttributeMaxDynamicSharedMemorySize, SMEM_BYTES);

    vt_kernel<<<dim3(8, BB), 256>>>(U, Wattn);
    main_kernel<<<dim3(NT, BB), 256, SMEM_BYTES>>>(H, U, Mm, tok, Wcls, out);
}

// round 16
// speedup vs baseline: 1.3202x; 1.1679x over previous
#include <cuda_runtime.h>
#include <cuda_bf16.h>
#include <cuda_fp16.h>
#include <cstdint>

#define BB 32
#define PP 4096
#define QQ 64
#define DD 128
#define NT 9
#define NEGBIG (-1e30f)
#define POSBIG (1e30f)

// ---- main kernel smem layout (32-bit words) ----
#define SM_UHI   0        // U hi packed (fp16) [qp*136 + d]   32*136 = 4352
#define SM_ULO   4352     // U lo packed (fp16)                 4352
#define SM_VTHI  8704     // Vt hi packed (bf16) [dp*72 + q]   64*72  = 4608
#define SM_VTLO  13312    // Vt lo packed (bf16)                4608
#define SM_HC    17920    // per warp c2q half buffer 16*68 = 1088; 8*1088 = 8704
#define SM_MZ    26624    // per warp row (m, invz) 16*2        8*32 = 256
#define SM_TOK   26880    // tok ints                           512
#define SM_MZS   27392    // warp M/Z                           16
#define SM_EEV   27408    // per warp eev[16]                   8*16 = 128
#define SM_TOTAL 27536
#define SMEM_BYTES (SM_TOTAL * 4)

// device scratch (zero-initialized)
__device__ float g_Vt[BB * DD * QQ];      // Vt[b][d][q]
__device__ float g_part[BB * NT * 1024];  // per (b,tile) partials
__device__ int   g_cnt[BB];               // arrival counters (left 0 after each call)

// ---------------------------------------------------------------------------
__device__ __forceinline__ void mma_bf16(float* d,
    uint32_t a0, uint32_t a1, uint32_t a2, uint32_t a3,
    uint32_t b0, uint32_t b1)
{
    asm volatile(
        "mma.sync.aligned.m16n8k16.row.col.f32.bf16.bf16.f32 "
        "{%0,%1,%2,%3}, {%4,%5,%6,%7}, {%8,%9}, {%0,%1,%2,%3};"
        : "+f"(d[0]), "+f"(d[1]), "+f"(d[2]), "+f"(d[3])
        : "r"(a0), "r"(a1), "r"(a2), "r"(a3), "r"(b0), "r"(b1));
}

__device__ __forceinline__ void mma_f16(float* d,
    uint32_t a0, uint32_t a1, uint32_t a2, uint32_t a3,
    uint32_t b0, uint32_t b1)
{
    asm volatile(
        "mma.sync.aligned.m16n8k16.row.col.f32.f16.f16.f32 "
        "{%0,%1,%2,%3}, {%4,%5,%6,%7}, {%8,%9}, {%0,%1,%2,%3};"
        : "+f"(d[0]), "+f"(d[1]), "+f"(d[2]), "+f"(d[3])
        : "r"(a0), "r"(a1), "r"(a2), "r"(a3), "r"(b0), "r"(b1));
}

// bf16 split (x = hi + lo + O(2^-17 x))
__device__ __forceinline__ void packsplit(float x0, float x1, uint32_t& hi, uint32_t& lo) {
    __nv_bfloat162 h = __float22bfloat162_rn(make_float2(x0, x1));
    float2 hf = __bfloat1622float2(h);
    __nv_bfloat162 l = __float22bfloat162_rn(make_float2(x0 - hf.x, x1 - hf.y));
    hi = *reinterpret_cast<uint32_t*>(&h);
    lo = *reinterpret_cast<uint32_t*>(&l);
}

// fp16 split (x = hi + lo + O(2^-23 x))
__device__ __forceinline__ void packsplit_h(float x0, float x1, uint32_t& hi, uint32_t& lo) {
    __half2 h = __float22half2_rn(make_float2(x0, x1));
    float2 hf = __half22float2(h);
    __half2 l = __float22half2_rn(make_float2(x0 - hf.x, x1 - hf.y));
    hi = *reinterpret_cast<uint32_t*>(&h);
    lo = *reinterpret_cast<uint32_t*>(&l);
}

// single fp16x2 pack (for softmax weights; error 2^-12 relative)
__device__ __forceinline__ uint32_t pack_h(float x0, float x1) {
    __half2 h = __float22half2_rn(make_float2(x0, x1));
    return *reinterpret_cast<uint32_t*>(&h);
}

// ---------------------------------------------------------------------------
// Kernel 1: Vt[b][d][q] = sum_e W[d,e]*U[b,q,e] (fp32 exact). grid (8,32).
// ---------------------------------------------------------------------------
__global__ void vt_kernel(const float* __restrict__ U, const float* __restrict__ W) {
    __shared__ float U_s[QQ * 129];
    __shared__ float W_s[16 * DD];
    int b = blockIdx.y, dbase = blockIdx.x * 16, tid = threadIdx.x;

    const float* Ub = U + (size_t)b * QQ * DD;
    for (int i = tid; i < QQ * DD; i += 256)
        U_s[(i >> 7) * 129 + (i & 127)] = Ub[i];
    for (int i = tid; i < 16 * DD; i += 256)
        W_s[i] = W[(size_t)dbase * DD + i];
    __syncthreads();

    int q = tid & 63, dg = tid >> 6;
    float acc[4] = {0.f, 0.f, 0.f, 0.f};
#pragma unroll 4
    for (int e = 0; e < DD; e++) {
        float u = U_s[q * 129 + e];
#pragma unroll
        for (int k = 0; k < 4; k++)
            acc[k] += u * W_s[(dg * 4 + k) * DD + e];
    }
#pragma unroll
    for (int k = 0; k < 4; k++)
        g_Vt[((size_t)b * DD + dbase + dg * 4 + k) * QQ + q] = acc[k];
}

// ---------------------------------------------------------------------------
// Kernel 2: fused attention (bf16-split S, fp16 2-term c2q) + pooling + finalize.
// grid (NT=9, 32), 256 threads, 2 CTAs/SM. Tiles 0-4: 4 chunks; 5-8: 3 chunks.
// ---------------------------------------------------------------------------
__global__ void __launch_bounds__(256, 2) main_kernel(
    const float* __restrict__ H, const float* __restrict__ U,
    const float* __restrict__ Mm, const int* __restrict__ tok,
    const float* __restrict__ Wcls, float* __restrict__ out)
{
    extern __shared__ float sm[];
    uint32_t* U_hi  = (uint32_t*)(sm + SM_UHI);
    uint32_t* U_lo  = (uint32_t*)(sm + SM_ULO);
    uint32_t* Vt_hi = (uint32_t*)(sm + SM_VTHI);
    uint32_t* Vt_lo = (uint32_t*)(sm + SM_VTLO);
    float*    hc_sb = sm + SM_HC;
    float*    mz_sb = sm + SM_MZ;
    int*      tok_s = (int*)(sm + SM_TOK);
    float*    mzs   = sm + SM_MZS;
    float*    eev_sb = sm + SM_EEV;
    float*    red   = sm + SM_HC;   // alias: HC dead by the time red is used
    __shared__ int s_last;

    int t = blockIdx.x, b = blockIdx.y;
    int nit    = (t < 5) ? 4 : 3;                       // chunks this tile
    int c0     = (t < 5) ? 4 * t : 20 + 3 * (t - 5);    // first chunk index
    int pstart = c0 * 128;
    int tid = threadIdx.x, wid = tid >> 5, lane = tid & 31;
    int g = lane >> 2, tg = lane & 3;

    // ---- stage packed U (fp16 pairs over q), packed Vt (bf16 pairs over d), tok ----
    const float* Ub = U + (size_t)b * QQ * DD;
    for (int i = tid; i < 32 * DD; i += 256) {
        int pq = i >> 7, d = i & 127;
        uint32_t hi, lo;
        packsplit_h(Ub[(2 * pq) * DD + d], Ub[(2 * pq + 1) * DD + d], hi, lo);
        U_hi[pq * 136 + d] = hi; U_lo[pq * 136 + d] = lo;
    }
    const float* Vtb = g_Vt + (size_t)b * DD * QQ;
    for (int i = tid; i < 64 * QQ; i += 256) {
        int pd = i >> 6, q = i & 63;
        uint32_t hi, lo;
        packsplit(Vtb[(2 * pd) * QQ + q], Vtb[(2 * pd + 1) * QQ + q], hi, lo);
        Vt_hi[pd * 72 + q] = hi; Vt_lo[pd * 72 + q] = lo;
    }
    const int* tokb = tok + (size_t)b * PP + pstart;
    for (int i = tid; i < nit * 128; i += 256) tok_s[i] = tokb[i];
    __syncthreads();

    float* myhc = hc_sb + wid * 1088;   // 16 rows * 68 (half-width c2q bounce)
    float* mymz = mz_sb + wid * 32;
    float* myee = eev_sb + wid * 16;

    // per-warp running partials (lane covers d = 4*lane + j)
    float pm_h[4], pm_c[4], pm_hc[4], pm_m[4], mnh[4], qacc[4];
#pragma unroll
    for (int j = 0; j < 4; j++) {
        pm_h[j] = NEGBIG; pm_c[j] = NEGBIG; pm_hc[j] = NEGBIG; pm_m[j] = NEGBIG;
        mnh[j] = POSBIG;  qacc[j] = 0.f;
    }
    float Mw = NEGBIG, Zw = 0.f;

    // loop-carried H A-fragment prefetch (covers it-boundary latency)
    const float* Hp0 = H + ((size_t)b * PP + pstart + wid * 16) * DD;
    float2 f0 = *(const float2*)(Hp0 + g * DD + 2 * tg);
    float2 f1 = *(const float2*)(Hp0 + (g + 8) * DD + 2 * tg);
    float2 f2 = *(const float2*)(Hp0 + g * DD + 8 + 2 * tg);
    float2 f3 = *(const float2*)(Hp0 + (g + 8) * DD + 8 + 2 * tg);

    for (int it = 0; it < nit; it++) {
        const float* Hp = Hp0 + (size_t)it * 128 * DD;
        const float* Mp = Mm + (Hp - H);

        // ---- S = H . Vt^T (3-term bf16 split) ----
        float sacc[8][4];
#pragma unroll
        for (int nt = 0; nt < 8; nt++)
            sacc[nt][0] = sacc[nt][1] = sacc[nt][2] = sacc[nt][3] = 0.f;

#pragma unroll
        for (int kt = 0; kt < 8; kt++) {
            uint32_t ah0, al0, ah1, al1, ah2, al2, ah3, al3;
            packsplit(f0.x, f0.y, ah0, al0);
            packsplit(f1.x, f1.y, ah1, al1);
            packsplit(f2.x, f2.y, ah2, al2);
            packsplit(f3.x, f3.y, ah3, al3);
            {   // prefetch: next kt, or next it's kt=0 (covered by c2q+pooling)
                const float* nxt = (kt < 7) ? (Hp + 16 * (kt + 1))
                                : ((it < nit - 1) ? (Hp + 128 * DD) : Hp);  // last it: dummy
                f0 = *(const float2*)(nxt + g * DD + 2 * tg);
                f1 = *(const float2*)(nxt + (g + 8) * DD + 2 * tg);
                f2 = *(const float2*)(nxt + g * DD + 8 + 2 * tg);
                f3 = *(const float2*)(nxt + (g + 8) * DD + 8 + 2 * tg);
            }
#pragma unroll
            for (int ch = 0; ch < 2; ch++) {
                uint32_t bh[4][2], bl[4][2];
#pragma unroll
                for (int j = 0; j < 4; j++) {
                    int c = 8 * (4 * ch + j) + g;
                    bh[j][0] = Vt_hi[(8 * kt + tg) * 72 + c];
                    bh[j][1] = Vt_hi[(8 * kt + tg + 4) * 72 + c];
                    bl[j][0] = Vt_lo[(8 * kt + tg) * 72 + c];
                    bl[j][1] = Vt_lo[(8 * kt + tg + 4) * 72 + c];
                }
#pragma unroll
                for (int j = 0; j < 4; j++)
                    mma_bf16(sacc[4 * ch + j], ah0, ah1, ah2, ah3, bh[j][0], bh[j][1]);
#pragma unroll
                for (int j = 0; j < 4; j++)
                    mma_bf16(sacc[4 * ch + j], ah0, ah1, ah2, ah3, bl[j][0], bl[j][1]);
#pragma unroll
                for (int j = 0; j < 4; j++)
                    mma_bf16(sacc[4 * ch + j], al0, al1, al2, al3, bh[j][0], bh[j][1]);
            }
        }

        // ---- softmax over q: rows g and g+8 ----
        float m0 = NEGBIG, m1 = NEGBIG;
#pragma unroll
        for (int nt = 0; nt < 8; nt++) {
            m0 = fmaxf(m0, fmaxf(sacc[nt][0], sacc[nt][1]));
            m1 = fmaxf(m1, fmaxf(sacc[nt][2], sacc[nt][3]));
        }
        m0 = fmaxf(m0, __shfl_xor_sync(0xffffffffu, m0, 1));
        m0 = fmaxf(m0, __shfl_xor_sync(0xffffffffu, m0, 2));
        m1 = fmaxf(m1, __shfl_xor_sync(0xffffffffu, m1, 1));
        m1 = fmaxf(m1, __shfl_xor_sync(0xffffffffu, m1, 2));

        float z0 = 0.f, z1 = 0.f;
#pragma unroll
        for (int nt = 0; nt < 8; nt++) {
            sacc[nt][0] = __expf(sacc[nt][0] - m0);
            sacc[nt][1] = __expf(sacc[nt][1] - m0);
            sacc[nt][2] = __expf(sacc[nt][2] - m1);
            sacc[nt][3] = __expf(sacc[nt][3] - m1);
            z0 += sacc[nt][0] + sacc[nt][1];
            z1 += sacc[nt][2] + sacc[nt][3];
        }
        z0 += __shfl_xor_sync(0xffffffffu, z0, 1);
        z0 += __shfl_xor_sync(0xffffffffu, z0, 2);
        z1 += __shfl_xor_sync(0xffffffffu, z1, 1);
        z1 += __shfl_xor_sync(0xffffffffu, z1, 2);

        if (tg == 0) {      // store m and 1/z (z used only for normalization)
            mymz[2 * g] = m0;           mymz[2 * g + 1] = 1.0f / z0;
            mymz[2 * (g + 8)] = m1;     mymz[2 * (g + 8) + 1] = 1.0f / z1;
        }

        // ---- pack e into single fp16 c2q A-fragments (S C-frag == c2q A-frag) ----
        uint32_t ea[4][4];
#pragma unroll
        for (int kt = 0; kt < 4; kt++) {
            ea[kt][0] = pack_h(sacc[2 * kt][0],     sacc[2 * kt][1]);
            ea[kt][1] = pack_h(sacc[2 * kt][2],     sacc[2 * kt][3]);
            ea[kt][2] = pack_h(sacc[2 * kt + 1][0], sacc[2 * kt + 1][1]);
            ea[kt][3] = pack_h(sacc[2 * kt + 1][2], sacc[2 * kt + 1][3]);
        }
        __syncwarp();   // mymz visible to all lanes

        // ---- per-iteration row stats, computed ONCE; eev parked in smem ----
        int rbase = (lane >> 4) * 8;    // this lane covers rows rbase..rbase+7
        float m16, z16, e1, e2;
        {
            float mloc = NEGBIG;
#pragma unroll
            for (int r = 0; r < 8; r++)
                mloc = fmaxf(mloc, mymz[2 * (rbase + r)]);
            float zloc = 0.f;
#pragma unroll
            for (int r = 0; r < 8; r++) {
                float e = __expf(mymz[2 * (rbase + r)] - mloc);
                zloc += e;
                if ((lane & 15) == 0) myee[rbase + r] = e;   // lanes 0,16 write
            }
            float mo = __shfl_xor_sync(0xffffffffu, mloc, 16);
            float zo = __shfl_xor_sync(0xffffffffu, zloc, 16);
            m16 = fmaxf(mloc, mo);
            e1  = __expf(mloc - m16);
            e2  = __expf(mo - m16);
            z16 = zloc * e1 + zo * e2;
        }
        __syncwarp();

        // ---- c2q in two d-column halves (fp16 2-term); all-lane pooling per half ----
#pragma unroll
        for (int half = 0; half < 2; half++) {
            float cacc[8][4];
#pragma unroll
            for (int ntl = 0; ntl < 8; ntl++)
                cacc[ntl][0] = cacc[ntl][1] = cacc[ntl][2] = cacc[ntl][3] = 0.f;

#pragma unroll
            for (int kt = 0; kt < 4; kt++) {
#pragma unroll
                for (int ch = 0; ch < 2; ch++) {
                    uint32_t bh[4][2], bl[4][2];
#pragma unroll
                    for (int j = 0; j < 4; j++) {
                        int c = 64 * half + 8 * (4 * ch + j) + g;
                        int r0i = (8 * kt + tg) * 136 + c;
                        int r1i = (8 * kt + tg + 4) * 136 + c;
                        bh[j][0] = U_hi[r0i]; bh[j][1] = U_hi[r1i];
                        bl[j][0] = U_lo[r0i]; bl[j][1] = U_lo[r1i];
                    }
#pragma unroll
                    for (int j = 0; j < 4; j++)
                        mma_f16(cacc[4 * ch + j], ea[kt][0], ea[kt][1], ea[kt][2], ea[kt][3], bh[j][0], bh[j][1]);
#pragma unroll
                    for (int j = 0; j < 4; j++)
                        mma_f16(cacc[4 * ch + j], ea[kt][0], ea[kt][1], ea[kt][2], ea[kt][3], bl[j][0], bl[j][1]);
                }
            }
            __syncwarp();   // previous half's pooling reads done
#pragma unroll
            for (int ntl = 0; ntl < 8; ntl++) {
                *(float2*)(myhc + g * 68 + 8 * ntl + 2 * tg)       = make_float2(cacc[ntl][0], cacc[ntl][1]);
                *(float2*)(myhc + (g + 8) * 68 + 8 * ntl + 2 * tg) = make_float2(cacc[ntl][2], cacc[ntl][3]);
            }
            __syncwarp();

            // ---- all-lane pooling: pair (l, l^16) splits the 16 rows ----
            {
                int aq   = lane & 15;           // quad within this half
                int gcol = 64 * half + 4 * aq;  // global d column

                float s_h[4], s_c[4], s_hc[4], s_m[4], s_n[4], s_q[4];
#pragma unroll
                for (int j = 0; j < 4; j++) {
                    s_h[j] = NEGBIG; s_c[j] = NEGBIG; s_hc[j] = NEGBIG;
                    s_m[j] = NEGBIG; s_n[j] = POSBIG; s_q[j] = 0.f;
                }

#pragma unroll 4
                for (int r = 0; r < 8; r++) {
                    int row = rbase + r;
                    float invz = mymz[2 * row + 1];   // precomputed 1/z
                    float4 c4 = *(float4*)(myhc + row * 68 + 4 * aq);
                    float4 h4 = *(const float4*)(Hp + row * DD + gcol);
                    float4 m4 = *(const float4*)(Mp + row * DD + gcol);  // unconditional (MLP)
                    float cv[4] = {c4.x * invz, c4.y * invz, c4.z * invz, c4.w * invz};
                    float hv[4] = {h4.x, h4.y, h4.z, h4.w};
                    float mv[4] = {m4.x, m4.y, m4.z, m4.w};

                    float ee = myee[row];
#pragma unroll
                    for (int j = 0; j < 4; j++) s_q[j] += ee * hv[j];

                    bool v = (tok_s[it * 128 + wid * 16 + row] != 0);
#pragma unroll
                    for (int j = 0; j < 4; j++) {   // predicated, no branch
                        s_h[j]  = fmaxf(s_h[j],  v ? hv[j]        : NEGBIG);
                        s_c[j]  = fmaxf(s_c[j],  v ? cv[j]        : NEGBIG);
                        s_hc[j] = fmaxf(s_hc[j], v ? hv[j]*cv[j]  : NEGBIG);
                        s_m[j]  = fmaxf(s_m[j],  v ? mv[j]        : NEGBIG);
                        s_n[j]  = fminf(s_n[j],  v ? hv[j]        : POSBIG);
                    }
                }

                // pair merge (both lanes get merged values)
#pragma unroll
                for (int j = 0; j < 4; j++) {
                    s_h[j]  = fmaxf(s_h[j],  __shfl_xor_sync(0xffffffffu, s_h[j],  16));
                    s_c[j]  = fmaxf(s_c[j],  __shfl_xor_sync(0xffffffffu, s_c[j],  16));
                    s_hc[j] = fmaxf(s_hc[j], __shfl_xor_sync(0xffffffffu, s_hc[j], 16));
                    s_m[j]  = fmaxf(s_m[j],  __shfl_xor_sync(0xffffffffu, s_m[j],  16));
                    s_n[j]  = fminf(s_n[j],  __shfl_xor_sync(0xffffffffu, s_n[j],  16));
                }
                float qo[4];
#pragma unroll
                for (int j = 0; j < 4; j++) qo[j] = __shfl_xor_sync(0xffffffffu, s_q[j], 16);
#pragma unroll
                for (int j = 0; j < 4; j++) s_q[j] = s_q[j] * e1 + qo[j] * e2;

                // owner lane folds into persistent partials (its own quad)
                if ((lane >> 4) == half) {
                    float nM = fmaxf(Mw, m16);
                    float aa = __expf(Mw - nM);
                    float ee = __expf(m16 - nM);
#pragma unroll
                    for (int j = 0; j < 4; j++) qacc[j] = qacc[j] * aa + s_q[j] * ee;
                    Zw = Zw * aa + z16 * ee;
                    Mw = nM;
#pragma unroll
                    for (int j = 0; j < 4; j++) {
                        pm_h[j]  = fmaxf(pm_h[j],  s_h[j]);
                        pm_c[j]  = fmaxf(pm_c[j],  s_c[j]);
                        pm_hc[j] = fmaxf(pm_hc[j], s_hc[j]);
                        pm_m[j]  = fmaxf(pm_m[j],  s_m[j]);
                        mnh[j]   = fminf(mnh[j],   s_n[j]);
                    }
                }
            }
            __syncwarp();
        }
    }

    // ---------------- block reduction -> tile partials ----------------
    __syncthreads();
    if (lane == 0) { mzs[wid * 2] = Mw; mzs[wid * 2 + 1] = Zw; }
    __syncthreads();
    float Mb = mzs[0];
#pragma unroll
    for (int w = 1; w < 8; w++) Mb = fmaxf(Mb, mzs[2 * w]);

    float* pout = g_part + ((size_t)b * NT + t) * 1024;
    float sc = __expf(Mw - Mb);

    *(float4*)(red + wid * DD + 4 * lane) =
        make_float4(qacc[0] * sc, qacc[1] * sc, qacc[2] * sc, qacc[3] * sc);
    __syncthreads();
    if (tid < DD) {
        float r = 0.f;
#pragma unroll
        for (int w = 0; w < 8; w++) r += red[w * DD + tid];
        pout[tid] = r;
    }

#define BLK_MAXRED(arr, off)                                                   \
    do {                                                                       \
        __syncthreads();                                                       \
        *(float4*)(red + wid * DD + 4 * lane) =                                \
            make_float4((arr)[0], (arr)[1], (arr)[2], (arr)[3]);               \
        __syncthreads();                                                       \
        if (tid < DD) {                                                        \
            float r = red[tid];                                                \
            for (int w = 1; w < 8; w++) r = fmaxf(r, red[w * DD + tid]);       \
            pout[(off) + tid] = r;                                             \
        }                                                                      \
    } while (0)

    BLK_MAXRED(pm_h, 128);
    BLK_MAXRED(pm_c, 256);
    BLK_MAXRED(pm_hc, 384);
    BLK_MAXRED(pm_m, 512);

    __syncthreads();
    *(float4*)(red + wid * DD + 4 * lane) = make_float4(mnh[0], mnh[1], mnh[2], mnh[3]);
    __syncthreads();
    if (tid < DD) {
        float r = red[tid];
#pragma unroll
        for (int w = 1; w < 8; w++) r = fminf(r, red[w * DD + tid]);
        pout[768 + tid] = r;
    }
    if (tid == 0) {
        float Zt = 0.f;
#pragma unroll
        for (int w = 0; w < 8; w++) Zt += mzs[2 * w + 1] * __expf(mzs[2 * w] - Mb);
        pout[896] = Mb;
        pout[897] = Zt;
    }

    // ---------------- fused finalize: last block of batch b ----------------
    __syncthreads();
    __threadfence();
    if (tid == 0) s_last = (atomicAdd(&g_cnt[b], 1) == NT - 1) ? 1 : 0;
    __syncthreads();
    if (s_last) {
        __threadfence();
        float o0 = 0.f, o1 = 0.f;
        if (tid < DD) {
            int d = tid;
            const float* base = g_part + (size_t)b * NT * 1024;
            float Mg = NEGBIG;
#pragma unroll
            for (int tt = 0; tt < NT; tt++) Mg = fmaxf(Mg, base[tt * 1024 + 896]);
            float Z = 0.f, qa = 0.f;
            float ph = NEGBIG, pc = NEGBIG, phc = NEGBIG, pmx = NEGBIG, nh = POSBIG;
#pragma unroll
            for (int tt = 0; tt < NT; tt++) {
                const float* pt = base + tt * 1024;
                float scv = __expf(pt[896] - Mg);
                Z  += pt[897] * scv;
                qa += pt[d] * scv;
                ph  = fmaxf(ph,  pt[128 + d]);
                pc  = fmaxf(pc,  pt[256 + d]);
                phc = fmaxf(phc, pt[384 + d]);
                pmx = fmaxf(pmx, pt[512 + d]);
                nh  = fminf(nh,  pt[768 + d]);
            }
            float q2c = qa / Z;
            float phq = fmaxf(q2c * ph, q2c * nh);   // ph == masked max of H
            o0 = ph * Wcls[2 * d] + pc * Wcls[2 * (128 + d)] + phc * Wcls[2 * (256 + d)]
               + phq * Wcls[2 * (384 + d)] + pmx * Wcls[2 * (512 + d)];
            o1 = ph * Wcls[2 * d + 1] + pc * Wcls[2 * (128 + d) + 1] + phc * Wcls[2 * (256 + d) + 1]
               + phq * Wcls[2 * (384 + d) + 1] + pmx * Wcls[2 * (512 + d) + 1];
        }
        __syncthreads();
        float* r0 = red;
        float* r1 = red + 128;
        if (tid < DD) { r0[tid] = o0; r1[tid] = o1; }
        __syncthreads();
        for (int s = 64; s > 0; s >>= 1) {
            if (tid < s) { r0[tid] += r0[tid + s]; r1[tid] += r1[tid + s]; }
            __syncthreads();
        }
        if (tid == 0) {
            out[b * 2]     = r0[0];
            out[b * 2 + 1] = r1[0];
            g_cnt[b] = 0;   // reset for next graph replay
        }
    }
}

// ---------------------------------------------------------------------------
extern "C" void kernel_launch(void* const* d_in, const int* in_sizes, int n_in,
                              void* d_out, int out_size) {
    const float* H     = (const float*)d_in[0];
    const float* U     = (const float*)d_in[1];
    const float* Mm    = (const float*)d_in[2];
    const int*   tok   = (const int*)d_in[3];    // int32 on the wire
    const float* Wattn = (const float*)d_in[4];
    const float* Wcls  = (const float*)d_in[5];
    float*       out   = (float*)d_out;

    cudaFuncSetAttribute(main_kernel, cudaFuncAttributeMaxDynamicSharedMemorySize, SMEM_BYTES);

    vt_kernel<<<dim3(8, BB), 256>>>(U, Wattn);
    main_kernel<<<dim3(NT, BB), 256, SMEM_BYTES>>>(H, U, Mm, tok, Wcls, out);
}

// round 17
// speedup vs baseline: 1.3972x; 1.0584x over previous
#include <cuda_runtime.h>
#include <cuda_bf16.h>
#include <cuda_fp16.h>
#include <cstdint>

#define BB 32
#define PP 4096
#define QQ 64
#define DD 128
#define NT 9
#define NEGBIG (-1e30f)
#define POSBIG (1e30f)

// ---- main kernel smem layout (32-bit words) ----
#define SM_UHI   0        // U hi packed (fp16) [qp*136 + d]   32*136 = 4352
#define SM_ULO   4352     // U lo packed (fp16)                 4352
#define SM_VTHI  8704     // Vt hi packed (bf16) [dp*72 + q]   64*72  = 4608
#define SM_VTLO  13312    // Vt lo packed (bf16)                4608
#define SM_HC    17920    // per warp c2q half buffer 16*68 = 1088; 8*1088 = 8704
#define SM_MZ    26624    // per warp row (m, invz) 16*2        8*32 = 256
#define SM_TOK   26880    // tok ints                           512
#define SM_MZS   27392    // warp M/Z                           16
#define SM_EEV   27408    // per warp eev[16]                   8*16 = 128
#define SM_TOTAL 27536
#define SMEM_BYTES (SM_TOTAL * 4)

// device scratch (zero-initialized)
__device__ float g_Vt[BB * DD * QQ];      // Vt[b][d][q]
__device__ float g_part[BB * NT * 1024];  // per (b,tile) partials
__device__ int   g_cnt[BB];               // arrival counters (left 0 after each call)

// ---------------------------------------------------------------------------
__device__ __forceinline__ void mma_bf16(float* d,
    uint32_t a0, uint32_t a1, uint32_t a2, uint32_t a3,
    uint32_t b0, uint32_t b1)
{
    asm volatile(
        "mma.sync.aligned.m16n8k16.row.col.f32.bf16.bf16.f32 "
        "{%0,%1,%2,%3}, {%4,%5,%6,%7}, {%8,%9}, {%0,%1,%2,%3};"
        : "+f"(d[0]), "+f"(d[1]), "+f"(d[2]), "+f"(d[3])
        : "r"(a0), "r"(a1), "r"(a2), "r"(a3), "r"(b0), "r"(b1));
}

__device__ __forceinline__ void mma_f16(float* d,
    uint32_t a0, uint32_t a1, uint32_t a2, uint32_t a3,
    uint32_t b0, uint32_t b1)
{
    asm volatile(
        "mma.sync.aligned.m16n8k16.row.col.f32.f16.f16.f32 "
        "{%0,%1,%2,%3}, {%4,%5,%6,%7}, {%8,%9}, {%0,%1,%2,%3};"
        : "+f"(d[0]), "+f"(d[1]), "+f"(d[2]), "+f"(d[3])
        : "r"(a0), "r"(a1), "r"(a2), "r"(a3), "r"(b0), "r"(b1));
}

// bf16 split (x = hi + lo + O(2^-17 x))
__device__ __forceinline__ void packsplit(float x0, float x1, uint32_t& hi, uint32_t& lo) {
    __nv_bfloat162 h = __float22bfloat162_rn(make_float2(x0, x1));
    float2 hf = __bfloat1622float2(h);
    __nv_bfloat162 l = __float22bfloat162_rn(make_float2(x0 - hf.x, x1 - hf.y));
    hi = *reinterpret_cast<uint32_t*>(&h);
    lo = *reinterpret_cast<uint32_t*>(&l);
}

// fp16 split (x = hi + lo + O(2^-23 x))
__device__ __forceinline__ void packsplit_h(float x0, float x1, uint32_t& hi, uint32_t& lo) {
    __half2 h = __float22half2_rn(make_float2(x0, x1));
    float2 hf = __half22float2(h);
    __half2 l = __float22half2_rn(make_float2(x0 - hf.x, x1 - hf.y));
    hi = *reinterpret_cast<uint32_t*>(&h);
    lo = *reinterpret_cast<uint32_t*>(&l);
}

// single fp16x2 pack (for softmax weights)
__device__ __forceinline__ uint32_t pack_h(float x0, float x1) {
    __half2 h = __float22half2_rn(make_float2(x0, x1));
    return *reinterpret_cast<uint32_t*>(&h);
}

// ---------------------------------------------------------------------------
// Kernel 1: Vt[b][d][q] = sum_e W[d,e]*U[b,q,e] (fp32 exact). grid (8,32).
// ---------------------------------------------------------------------------
__global__ void vt_kernel(const float* __restrict__ U, const float* __restrict__ W) {
    __shared__ float U_s[QQ * 129];
    __shared__ float W_s[16 * DD];
    int b = blockIdx.y, dbase = blockIdx.x * 16, tid = threadIdx.x;

    const float* Ub = U + (size_t)b * QQ * DD;
    for (int i = tid; i < QQ * DD; i += 256)
        U_s[(i >> 7) * 129 + (i & 127)] = Ub[i];
    for (int i = tid; i < 16 * DD; i += 256)
        W_s[i] = W[(size_t)dbase * DD + i];
    __syncthreads();

    int q = tid & 63, dg = tid >> 6;
    float acc[4] = {0.f, 0.f, 0.f, 0.f};
#pragma unroll 4
    for (int e = 0; e < DD; e++) {
        float u = U_s[q * 129 + e];
#pragma unroll
        for (int k = 0; k < 4; k++)
            acc[k] += u * W_s[(dg * 4 + k) * DD + e];
    }
#pragma unroll
    for (int k = 0; k < 4; k++)
        g_Vt[((size_t)b * DD + dbase + dg * 4 + k) * QQ + q] = acc[k];
}

// ---------------------------------------------------------------------------
// Kernel 2: fused attention (bf16-split S, fp16 2-term c2q) + pooling + finalize.
// grid (NT=9, 32), 256 threads, 2 CTAs/SM. Tiles 0-4: 4 chunks; 5-8: 3 chunks.
// ---------------------------------------------------------------------------
__global__ void __launch_bounds__(256, 2) main_kernel(
    const float* __restrict__ H, const float* __restrict__ U,
    const float* __restrict__ Mm, const int* __restrict__ tok,
    const float* __restrict__ Wcls, float* __restrict__ out)
{
    extern __shared__ float sm[];
    uint32_t* U_hi  = (uint32_t*)(sm + SM_UHI);
    uint32_t* U_lo  = (uint32_t*)(sm + SM_ULO);
    uint32_t* Vt_hi = (uint32_t*)(sm + SM_VTHI);
    uint32_t* Vt_lo = (uint32_t*)(sm + SM_VTLO);
    float*    hc_sb = sm + SM_HC;
    float*    mz_sb = sm + SM_MZ;
    int*      tok_s = (int*)(sm + SM_TOK);
    float*    mzs   = sm + SM_MZS;
    float*    eev_sb = sm + SM_EEV;
    float*    red   = sm + SM_HC;   // alias: HC dead by the time red is used
    __shared__ int s_last;

    int t = blockIdx.x, b = blockIdx.y;
    int nit    = (t < 5) ? 4 : 3;                       // chunks this tile
    int c0     = (t < 5) ? 4 * t : 20 + 3 * (t - 5);    // first chunk index
    int pstart = c0 * 128;
    int tid = threadIdx.x, wid = tid >> 5, lane = tid & 31;
    int g = lane >> 2, tg = lane & 3;

    // ---- stage packed U (fp16 pairs over q), packed Vt (bf16 pairs over d), tok ----
    const float* Ub = U + (size_t)b * QQ * DD;
    for (int i = tid; i < 32 * DD; i += 256) {
        int pq = i >> 7, d = i & 127;
        uint32_t hi, lo;
        packsplit_h(Ub[(2 * pq) * DD + d], Ub[(2 * pq + 1) * DD + d], hi, lo);
        U_hi[pq * 136 + d] = hi; U_lo[pq * 136 + d] = lo;
    }
    const float* Vtb = g_Vt + (size_t)b * DD * QQ;
    for (int i = tid; i < 64 * QQ; i += 256) {
        int pd = i >> 6, q = i & 63;
        uint32_t hi, lo;
        packsplit(Vtb[(2 * pd) * QQ + q], Vtb[(2 * pd + 1) * QQ + q], hi, lo);
        Vt_hi[pd * 72 + q] = hi; Vt_lo[pd * 72 + q] = lo;
    }
    const int* tokb = tok + (size_t)b * PP + pstart;
    for (int i = tid; i < nit * 128; i += 256) tok_s[i] = tokb[i];
    __syncthreads();

    float* myhc = hc_sb + wid * 1088;   // 16 rows * 68 (half-width c2q bounce)
    float* mymz = mz_sb + wid * 32;
    float* myee = eev_sb + wid * 16;

    // per-warp running partials (lane covers d = 4*lane + j)
    float pm_h[4], pm_c[4], pm_hc[4], pm_m[4], mnh[4], qacc[4];
#pragma unroll
    for (int j = 0; j < 4; j++) {
        pm_h[j] = NEGBIG; pm_c[j] = NEGBIG; pm_hc[j] = NEGBIG; pm_m[j] = NEGBIG;
        mnh[j] = POSBIG;  qacc[j] = 0.f;
    }
    float Mw = NEGBIG, Zw = 0.f;

    // loop-carried H A-fragment prefetch (covers it-boundary latency)
    const float* Hp0 = H + ((size_t)b * PP + pstart + wid * 16) * DD;
    float2 f0 = *(const float2*)(Hp0 + g * DD + 2 * tg);
    float2 f1 = *(const float2*)(Hp0 + (g + 8) * DD + 2 * tg);
    float2 f2 = *(const float2*)(Hp0 + g * DD + 8 + 2 * tg);
    float2 f3 = *(const float2*)(Hp0 + (g + 8) * DD + 8 + 2 * tg);

    for (int it = 0; it < nit; it++) {
        const float* Hp = Hp0 + (size_t)it * 128 * DD;
        const float* Mp = Mm + (Hp - H);

        // ---- S = H . Vt^T (3-term bf16 split) ----
        float sacc[8][4];
#pragma unroll
        for (int nt = 0; nt < 8; nt++)
            sacc[nt][0] = sacc[nt][1] = sacc[nt][2] = sacc[nt][3] = 0.f;

#pragma unroll
        for (int kt = 0; kt < 8; kt++) {
            uint32_t ah0, al0, ah1, al1, ah2, al2, ah3, al3;
            packsplit(f0.x, f0.y, ah0, al0);
            packsplit(f1.x, f1.y, ah1, al1);
            packsplit(f2.x, f2.y, ah2, al2);
            packsplit(f3.x, f3.y, ah3, al3);
            {   // prefetch: next kt, or next it's kt=0 (covered by c2q+pooling)
                const float* nxt = (kt < 7) ? (Hp + 16 * (kt + 1))
                                : ((it < nit - 1) ? (Hp + 128 * DD) : Hp);  // last it: dummy
                f0 = *(const float2*)(nxt + g * DD + 2 * tg);
                f1 = *(const float2*)(nxt + (g + 8) * DD + 2 * tg);
                f2 = *(const float2*)(nxt + g * DD + 8 + 2 * tg);
                f3 = *(const float2*)(nxt + (g + 8) * DD + 8 + 2 * tg);
            }
#pragma unroll
            for (int ch = 0; ch < 2; ch++) {
                uint32_t bh[4][2], bl[4][2];
#pragma unroll
                for (int j = 0; j < 4; j++) {
                    int c = 8 * (4 * ch + j) + g;
                    bh[j][0] = Vt_hi[(8 * kt + tg) * 72 + c];
                    bh[j][1] = Vt_hi[(8 * kt + tg + 4) * 72 + c];
                    bl[j][0] = Vt_lo[(8 * kt + tg) * 72 + c];
                    bl[j][1] = Vt_lo[(8 * kt + tg + 4) * 72 + c];
                }
#pragma unroll
                for (int j = 0; j < 4; j++)
                    mma_bf16(sacc[4 * ch + j], ah0, ah1, ah2, ah3, bh[j][0], bh[j][1]);
#pragma unroll
                for (int j = 0; j < 4; j++)
                    mma_bf16(sacc[4 * ch + j], ah0, ah1, ah2, ah3, bl[j][0], bl[j][1]);
#pragma unroll
                for (int j = 0; j < 4; j++)
                    mma_bf16(sacc[4 * ch + j], al0, al1, al2, al3, bh[j][0], bh[j][1]);
            }
        }

        // ---- softmax over q: rows g and g+8 ----
        float m0 = NEGBIG, m1 = NEGBIG;
#pragma unroll
        for (int nt = 0; nt < 8; nt++) {
            m0 = fmaxf(m0, fmaxf(sacc[nt][0], sacc[nt][1]));
            m1 = fmaxf(m1, fmaxf(sacc[nt][2], sacc[nt][3]));
        }
        m0 = fmaxf(m0, __shfl_xor_sync(0xffffffffu, m0, 1));
        m0 = fmaxf(m0, __shfl_xor_sync(0xffffffffu, m0, 2));
        m1 = fmaxf(m1, __shfl_xor_sync(0xffffffffu, m1, 1));
        m1 = fmaxf(m1, __shfl_xor_sync(0xffffffffu, m1, 2));

        float z0 = 0.f, z1 = 0.f;
#pragma unroll
        for (int nt = 0; nt < 8; nt++) {
            sacc[nt][0] = __expf(sacc[nt][0] - m0);
            sacc[nt][1] = __expf(sacc[nt][1] - m0);
            sacc[nt][2] = __expf(sacc[nt][2] - m1);
            sacc[nt][3] = __expf(sacc[nt][3] - m1);
            z0 += sacc[nt][0] + sacc[nt][1];
            z1 += sacc[nt][2] + sacc[nt][3];
        }
        z0 += __shfl_xor_sync(0xffffffffu, z0, 1);
        z0 += __shfl_xor_sync(0xffffffffu, z0, 2);
        z1 += __shfl_xor_sync(0xffffffffu, z1, 1);
        z1 += __shfl_xor_sync(0xffffffffu, z1, 2);

        if (tg == 0) {      // store m and 1/z
            mymz[2 * g] = m0;           mymz[2 * g + 1] = 1.0f / z0;
            mymz[2 * (g + 8)] = m1;     mymz[2 * (g + 8) + 1] = 1.0f / z1;
        }

        // ---- pack e into single fp16 c2q A-fragments (S C-frag == c2q A-frag) ----
        uint32_t ea[4][4];
#pragma unroll
        for (int kt = 0; kt < 4; kt++) {
            ea[kt][0] = pack_h(sacc[2 * kt][0],     sacc[2 * kt][1]);
            ea[kt][1] = pack_h(sacc[2 * kt][2],     sacc[2 * kt][3]);
            ea[kt][2] = pack_h(sacc[2 * kt + 1][0], sacc[2 * kt + 1][1]);
            ea[kt][3] = pack_h(sacc[2 * kt + 1][2], sacc[2 * kt + 1][3]);
        }
        __syncwarp();   // mymz visible to all lanes

        // ---- per-iteration row stats, computed ONCE; eev parked in smem ----
        int rbase = (lane >> 4) * 8;    // this lane covers rows rbase..rbase+7
        float m16, z16, e1, e2;
        bool allv;
        {
            float mloc = NEGBIG;
#pragma unroll
            for (int r = 0; r < 8; r++)
                mloc = fmaxf(mloc, mymz[2 * (rbase + r)]);
            float zloc = 0.f;
#pragma unroll
            for (int r = 0; r < 8; r++) {
                float e = __expf(mymz[2 * (rbase + r)] - mloc);
                zloc += e;
                if ((lane & 15) == 0) myee[rbase + r] = e;   // lanes 0,16 write
            }
            float mo = __shfl_xor_sync(0xffffffffu, mloc, 16);
            float zo = __shfl_xor_sync(0xffffffffu, zloc, 16);
            m16 = fmaxf(mloc, mo);
            e1  = __expf(mloc - m16);
            e2  = __expf(mo - m16);
            z16 = zloc * e1 + zo * e2;

            // warp-uniform validity of this iteration's 16 rows
            bool vloc = true;
#pragma unroll
            for (int r = 0; r < 8; r++)
                vloc = vloc && (tok_s[it * 128 + wid * 16 + rbase + r] != 0);
            allv = __all_sync(0xffffffffu, vloc);
        }
        __syncwarp();

        // ---- c2q in two d-column halves (fp16 2-term); all-lane pooling per half ----
#pragma unroll
        for (int half = 0; half < 2; half++) {
            float cacc[8][4];
#pragma unroll
            for (int ntl = 0; ntl < 8; ntl++)
                cacc[ntl][0] = cacc[ntl][1] = cacc[ntl][2] = cacc[ntl][3] = 0.f;

#pragma unroll
            for (int kt = 0; kt < 4; kt++) {
#pragma unroll
                for (int ch = 0; ch < 2; ch++) {
                    uint32_t bh[4][2], bl[4][2];
#pragma unroll
                    for (int j = 0; j < 4; j++) {
                        int c = 64 * half + 8 * (4 * ch + j) + g;
                        int r0i = (8 * kt + tg) * 136 + c;
                        int r1i = (8 * kt + tg + 4) * 136 + c;
                        bh[j][0] = U_hi[r0i]; bh[j][1] = U_hi[r1i];
                        bl[j][0] = U_lo[r0i]; bl[j][1] = U_lo[r1i];
                    }
#pragma unroll
                    for (int j = 0; j < 4; j++)
                        mma_f16(cacc[4 * ch + j], ea[kt][0], ea[kt][1], ea[kt][2], ea[kt][3], bh[j][0], bh[j][1]);
#pragma unroll
                    for (int j = 0; j < 4; j++)
                        mma_f16(cacc[4 * ch + j], ea[kt][0], ea[kt][1], ea[kt][2], ea[kt][3], bl[j][0], bl[j][1]);
                }
            }
            __syncwarp();   // previous half's pooling reads done
#pragma unroll
            for (int ntl = 0; ntl < 8; ntl++) {
                *(float2*)(myhc + g * 68 + 8 * ntl + 2 * tg)       = make_float2(cacc[ntl][0], cacc[ntl][1]);
                *(float2*)(myhc + (g + 8) * 68 + 8 * ntl + 2 * tg) = make_float2(cacc[ntl][2], cacc[ntl][3]);
            }
            __syncwarp();

            // ---- all-lane pooling: pair (l, l^16) splits the 16 rows ----
            {
                int aq   = lane & 15;           // quad within this half
                int gcol = 64 * half + 4 * aq;  // global d column

                float s_h[4], s_c[4], s_hc[4], s_m[4], s_n[4], s_q[4];
#pragma unroll
                for (int j = 0; j < 4; j++) {
                    s_h[j] = NEGBIG; s_c[j] = NEGBIG; s_hc[j] = NEGBIG;
                    s_m[j] = NEGBIG; s_n[j] = POSBIG; s_q[j] = 0.f;
                }

                if (allv) {
                    // fast path: no pads in these 16 rows -> selects are no-ops
#pragma unroll 4
                    for (int r = 0; r < 8; r++) {
                        int row = rbase + r;
                        float invz = mymz[2 * row + 1];
                        float4 c4 = *(float4*)(myhc + row * 68 + 4 * aq);
                        float4 h4 = *(const float4*)(Hp + row * DD + gcol);
                        float4 m4 = *(const float4*)(Mp + row * DD + gcol);
                        float cv[4] = {c4.x * invz, c4.y * invz, c4.z * invz, c4.w * invz};
                        float hv[4] = {h4.x, h4.y, h4.z, h4.w};
                        float mv[4] = {m4.x, m4.y, m4.z, m4.w};
                        float ee = myee[row];
#pragma unroll
                        for (int j = 0; j < 4; j++) {
                            s_q[j]  += ee * hv[j];
                            s_h[j]  = fmaxf(s_h[j],  hv[j]);
                            s_c[j]  = fmaxf(s_c[j],  cv[j]);
                            s_hc[j] = fmaxf(s_hc[j], hv[j] * cv[j]);
                            s_m[j]  = fmaxf(s_m[j],  mv[j]);
                            s_n[j]  = fminf(s_n[j],  hv[j]);
                        }
                    }
                } else {
                    // slow path: per-row masked updates (rare)
#pragma unroll 4
                    for (int r = 0; r < 8; r++) {
                        int row = rbase + r;
                        float invz = mymz[2 * row + 1];
                        float4 c4 = *(float4*)(myhc + row * 68 + 4 * aq);
                        float4 h4 = *(const float4*)(Hp + row * DD + gcol);
                        float4 m4 = *(const float4*)(Mp + row * DD + gcol);
                        float cv[4] = {c4.x * invz, c4.y * invz, c4.z * invz, c4.w * invz};
                        float hv[4] = {h4.x, h4.y, h4.z, h4.w};
                        float mv[4] = {m4.x, m4.y, m4.z, m4.w};
                        float ee = myee[row];
#pragma unroll
                        for (int j = 0; j < 4; j++) s_q[j] += ee * hv[j];

                        bool v = (tok_s[it * 128 + wid * 16 + row] != 0);
#pragma unroll
                        for (int j = 0; j < 4; j++) {
                            s_h[j]  = fmaxf(s_h[j],  v ? hv[j]        : NEGBIG);
                            s_c[j]  = fmaxf(s_c[j],  v ? cv[j]        : NEGBIG);
                            s_hc[j] = fmaxf(s_hc[j], v ? hv[j]*cv[j]  : NEGBIG);
                            s_m[j]  = fmaxf(s_m[j],  v ? mv[j]        : NEGBIG);
                            s_n[j]  = fminf(s_n[j],  v ? hv[j]        : POSBIG);
                        }
                    }
                }

                // pair merge (both lanes get merged values)
#pragma unroll
                for (int j = 0; j < 4; j++) {
                    s_h[j]  = fmaxf(s_h[j],  __shfl_xor_sync(0xffffffffu, s_h[j],  16));
                    s_c[j]  = fmaxf(s_c[j],  __shfl_xor_sync(0xffffffffu, s_c[j],  16));
                    s_hc[j] = fmaxf(s_hc[j], __shfl_xor_sync(0xffffffffu, s_hc[j], 16));
                    s_m[j]  = fmaxf(s_m[j],  __shfl_xor_sync(0xffffffffu, s_m[j],  16));
                    s_n[j]  = fminf(s_n[j],  __shfl_xor_sync(0xffffffffu, s_n[j],  16));
                }
                float qo[4];
#pragma unroll
                for (int j = 0; j < 4; j++) qo[j] = __shfl_xor_sync(0xffffffffu, s_q[j], 16);
#pragma unroll
                for (int j = 0; j < 4; j++) s_q[j] = s_q[j] * e1 + qo[j] * e2;

                // owner lane folds into persistent partials (its own quad)
                if ((lane >> 4) == half) {
                    float nM = fmaxf(Mw, m16);
                    float aa = __expf(Mw - nM);
                    float ee = __expf(m16 - nM);
#pragma unroll
                    for (int j = 0; j < 4; j++) qacc[j] = qacc[j] * aa + s_q[j] * ee;
                    Zw = Zw * aa + z16 * ee;
                    Mw = nM;
#pragma unroll
                    for (int j = 0; j < 4; j++) {
                        pm_h[j]  = fmaxf(pm_h[j],  s_h[j]);
                        pm_c[j]  = fmaxf(pm_c[j],  s_c[j]);
                        pm_hc[j] = fmaxf(pm_hc[j], s_hc[j]);
                        pm_m[j]  = fmaxf(pm_m[j],  s_m[j]);
                        mnh[j]   = fminf(mnh[j],   s_n[j]);
                    }
                }
            }
            __syncwarp();
        }
    }

    // ---------------- block reduction -> tile partials ----------------
    __syncthreads();
    if (lane == 0) { mzs[wid * 2] = Mw; mzs[wid * 2 + 1] = Zw; }
    __syncthreads();
    float Mb = mzs[0];
#pragma unroll
    for (int w = 1; w < 8; w++) Mb = fmaxf(Mb, mzs[2 * w]);

    float* pout = g_part + ((size_t)b * NT + t) * 1024;
    float sc = __expf(Mw - Mb);

    *(float4*)(red + wid * DD + 4 * lane) =
        make_float4(qacc[0] * sc, qacc[1] * sc, qacc[2] * sc, qacc[3] * sc);
    __syncthreads();
    if (tid < DD) {
        float r = 0.f;
#pragma unroll
        for (int w = 0; w < 8; w++) r += red[w * DD + tid];
        pout[tid] = r;
    }

#define BLK_MAXRED(arr, off)                                                   \
    do {                                                                       \
        __syncthreads();                                                       \
        *(float4*)(red + wid * DD + 4 * lane) =                                \
            make_float4((arr)[0], (arr)[1], (arr)[2], (arr)[3]);               \
        __syncthreads();                                                       \
        if (tid < DD) {                                                        \
            float r = red[tid];                                                \
            for (int w = 1; w < 8; w++) r = fmaxf(r, red[w * DD + tid]);       \
            pout[(off) + tid] = r;                                             \
        }                                                                      \
    } while (0)

    BLK_MAXRED(pm_h, 128);
    BLK_MAXRED(pm_c, 256);
    BLK_MAXRED(pm_hc, 384);
    BLK_MAXRED(pm_m, 512);

    __syncthreads();
    *(float4*)(red + wid * DD + 4 * lane) = make_float4(mnh[0], mnh[1], mnh[2], mnh[3]);
    __syncthreads();
    if (tid < DD) {
        float r = red[tid];
#pragma unroll
        for (int w = 1; w < 8; w++) r = fminf(r, red[w * DD + tid]);
        pout[768 + tid] = r;
    }
    if (tid == 0) {
        float Zt = 0.f;
#pragma unroll
        for (int w = 0; w < 8; w++) Zt += mzs[2 * w + 1] * __expf(mzs[2 * w] - Mb);
        pout[896] = Mb;
        pout[897] = Zt;
    }

    // ---------------- fused finalize: last block of batch b ----------------
    __syncthreads();
    __threadfence();
    if (tid == 0) s_last = (atomicAdd(&g_cnt[b], 1) == NT - 1) ? 1 : 0;
    __syncthreads();
    if (s_last) {
        __threadfence();
        float o0 = 0.f, o1 = 0.f;
        if (tid < DD) {
            int d = tid;
            const float* base = g_part + (size_t)b * NT * 1024;
            float Mg = NEGBIG;
#pragma unroll
            for (int tt = 0; tt < NT; tt++) Mg = fmaxf(Mg, base[tt * 1024 + 896]);
            float Z = 0.f, qa = 0.f;
            float ph = NEGBIG, pc = NEGBIG, phc = NEGBIG, pmx = NEGBIG, nh = POSBIG;
#pragma unroll
            for (int tt = 0; tt < NT; tt++) {
                const float* pt = base + tt * 1024;
                float scv = __expf(pt[896] - Mg);
                Z  += pt[897] * scv;
                qa += pt[d] * scv;
                ph  = fmaxf(ph,  pt[128 + d]);
                pc  = fmaxf(pc,  pt[256 + d]);
                phc = fmaxf(phc, pt[384 + d]);
                pmx = fmaxf(pmx, pt[512 + d]);
                nh  = fminf(nh,  pt[768 + d]);
            }
            float q2c = qa / Z;
            float phq = fmaxf(q2c * ph, q2c * nh);   // ph == masked max of H
            o0 = ph * Wcls[2 * d] + pc * Wcls[2 * (128 + d)] + phc * Wcls[2 * (256 + d)]
               + phq * Wcls[2 * (384 + d)] + pmx * Wcls[2 * (512 + d)];
            o1 = ph * Wcls[2 * d + 1] + pc * Wcls[2 * (128 + d) + 1] + phc * Wcls[2 * (256 + d) + 1]
               + phq * Wcls[2 * (384 + d) + 1] + pmx * Wcls[2 * (512 + d) + 1];
        }
        __syncthreads();
        float* r0 = red;
        float* r1 = red + 128;
        if (tid < DD) { r0[tid] = o0; r1[tid] = o1; }
        __syncthreads();
        for (int s = 64; s > 0; s >>= 1) {
            if (tid < s) { r0[tid] += r0[tid + s]; r1[tid] += r1[tid + s]; }
            __syncthreads();
        }
        if (tid == 0) {
            out[b * 2]     = r0[0];
            out[b * 2 + 1] = r1[0];
            g_cnt[b] = 0;   // reset for next graph replay
        }
    }
}

// ---------------------------------------------------------------------------
extern "C" void kernel_launch(void* const* d_in, const int* in_sizes, int n_in,
                              void* d_out, int out_size) {
    const float* H     = (const float*)d_in[0];
    const float* U     = (const float*)d_in[1];
    const float* Mm    = (const float*)d_in[2];
    const int*   tok   = (const int*)d_in[3];    // int32 on the wire
    const float* Wattn = (const float*)d_in[4];
    const float* Wcls  = (const float*)d_in[5];
    float*       out   = (float*)d_out;

    cudaFuncSetAttribute(main_kernel, cudaFuncAttributeMaxDynamicSharedMemorySize, SMEM_BYTES);

    vt_kernel<<<dim3(8, BB), 256>>>(U, Wattn);
    main_kernel<<<dim3(NT, BB), 256, SMEM_BYTES>>>(H, U, Mm, tok, Wcls, out);
}